// round 1
// baseline (speedup 1.0000x reference)
#include <cuda_runtime.h>
#include <math.h>
#include <stdint.h>

// ---------------------------------------------------------------------------
// Transformer block: B=16, S=512, D=1024, H=16, HD=64, FF=4096
// x -> LN1 -> attn -> x+2a -> [LN2 -> MLP -> add] x2
// TF32 tensor-core GEMMs (mma.sync.m16n8k8), fused epilogues.
// ---------------------------------------------------------------------------

#define BATCH   16
#define SEQ     512
#define DMODEL  1024
#define NHEAD   16
#define HDIM    64
#define FFDIM   4096
#define ROWS    (BATCH * SEQ)          // 8192

// Scratch (static device arrays -- allocation-free rule)
__device__ float g_c  [ROWS * DMODEL];
__device__ float g_q  [ROWS * DMODEL];
__device__ float g_k  [ROWS * DMODEL];
__device__ float g_v  [ROWS * DMODEL];
__device__ float g_s  [(size_t)BATCH * NHEAD * SEQ * SEQ];   // 256 MB
__device__ float g_at [ROWS * DMODEL];
__device__ float g_x1 [ROWS * DMODEL];
__device__ float g_x2 [ROWS * DMODEL];
__device__ float g_h  [ROWS * FFDIM];                        // 128 MB

// ---------------------------------------------------------------------------
// helpers
// ---------------------------------------------------------------------------
__device__ __forceinline__ float to_tf32(float x) {
    float r;
    asm("cvt.rna.tf32.f32 %0, %1;" : "=f"(r) : "f"(x));
    return r;
}

__device__ __forceinline__ float gelu_tanh(float x) {
    float x3 = x * x * x;
    float u  = 0.7978845608028654f * (x + 0.044715f * x3);
    return 0.5f * x * (1.0f + tanhf(u));
}

__device__ __forceinline__ void mma_tf32(float* c, const uint32_t* a, const uint32_t* b) {
    asm volatile(
        "mma.sync.aligned.m16n8k8.row.col.f32.tf32.tf32.f32 "
        "{%0,%1,%2,%3}, {%4,%5,%6,%7}, {%8,%9}, {%0,%1,%2,%3};\n"
        : "+f"(c[0]), "+f"(c[1]), "+f"(c[2]), "+f"(c[3])
        : "r"(a[0]), "r"(a[1]), "r"(a[2]), "r"(a[3]),
          "r"(b[0]), "r"(b[1]));
}

// ---------------------------------------------------------------------------
// LayerNorm: one block per row of 1024
// ---------------------------------------------------------------------------
__global__ void ln_kernel(const float* __restrict__ x,
                          const float* __restrict__ scale,
                          float* __restrict__ out) {
    int row = blockIdx.x, tid = threadIdx.x;
    const float4* xr = (const float4*)(x + (size_t)row * DMODEL);
    float4 v = xr[tid];
    float s = v.x + v.y + v.z + v.w;
    float q = v.x * v.x + v.y * v.y + v.z * v.z + v.w * v.w;
    #pragma unroll
    for (int o = 16; o > 0; o >>= 1) {
        s += __shfl_xor_sync(0xffffffffu, s, o);
        q += __shfl_xor_sync(0xffffffffu, q, o);
    }
    __shared__ float ss[8], qq[8];
    if ((tid & 31) == 0) { ss[tid >> 5] = s; qq[tid >> 5] = q; }
    __syncthreads();
    if (tid == 0) {
        float ts = 0.f, tq = 0.f;
        #pragma unroll
        for (int i = 0; i < 8; i++) { ts += ss[i]; tq += qq[i]; }
        ss[0] = ts; qq[0] = tq;
    }
    __syncthreads();
    float mean = ss[0] * (1.0f / DMODEL);
    float var  = qq[0] * (1.0f / DMODEL) - mean * mean;
    float r    = rsqrtf(var + 1e-6f);
    float4 sc  = ((const float4*)scale)[tid];
    float4 o;
    o.x = (v.x - mean) * r * sc.x;
    o.y = (v.y - mean) * r * sc.y;
    o.z = (v.z - mean) * r * sc.z;
    o.w = (v.w - mean) * r * sc.w;
    ((float4*)(out + (size_t)row * DMODEL))[tid] = o;
}

// ---------------------------------------------------------------------------
// Softmax over rows of 512 (in-place), with 1/sqrt(HD)=0.125 pre-scale
// ---------------------------------------------------------------------------
__global__ void softmax_kernel(float* __restrict__ s) {
    size_t row = blockIdx.x;
    float2* p = (float2*)(s + row * SEQ);
    int tid = threadIdx.x;
    float2 v = p[tid];
    v.x *= 0.125f; v.y *= 0.125f;
    float m = fmaxf(v.x, v.y);
    #pragma unroll
    for (int o = 16; o > 0; o >>= 1) m = fmaxf(m, __shfl_xor_sync(0xffffffffu, m, o));
    __shared__ float rm[8], rs[8];
    if ((tid & 31) == 0) rm[tid >> 5] = m;
    __syncthreads();
    if (tid == 0) {
        float t = rm[0];
        #pragma unroll
        for (int i = 1; i < 8; i++) t = fmaxf(t, rm[i]);
        rm[0] = t;
    }
    __syncthreads();
    m = rm[0];
    float e0 = __expf(v.x - m), e1 = __expf(v.y - m);
    float sum = e0 + e1;
    #pragma unroll
    for (int o = 16; o > 0; o >>= 1) sum += __shfl_xor_sync(0xffffffffu, sum, o);
    if ((tid & 31) == 0) rs[tid >> 5] = sum;
    __syncthreads();
    if (tid == 0) {
        float t = 0.f;
        #pragma unroll
        for (int i = 0; i < 8; i++) t += rs[i];
        rs[0] = t;
    }
    __syncthreads();
    float inv = 1.0f / rs[0];
    p[tid] = make_float2(e0 * inv, e1 * inv);
}

// ---------------------------------------------------------------------------
// Generic batched TF32 GEMM.  C[M,N] = A[M,K] * B[K,N]   (A row-major)
// TRANSB=false: B[k,n] = Bptr[k*ldb + n]
// TRANSB=true : B[k,n] = Bptr[n*ldb + k]    (NT, for Q@K^T)
// Batch z: off = (z/innerCount)*outer + (z%innerCount)*inner (per matrix)
// EPI: 0 none | 1 gelu(acc+bias) | 2 acc+bias+res | 3 res+2*acc
// ---------------------------------------------------------------------------
template<int BM, int BN, int WM, int WN, bool TRANSB, int EPI>
__global__ void __launch_bounds__(256)
gemm_kernel(const float* __restrict__ A, long long aOuter, long long aInner, int lda,
            const float* __restrict__ B, long long bOuter, long long bInner, int ldb,
            float* __restrict__ C, long long cOuter, long long cInner, int ldc,
            const float* __restrict__ bias,
            const float* __restrict__ res,
            int M, int N, int K, int innerCount) {
    constexpr int BK = 32;
    constexpr int WARPS_M = BM / WM;
    constexpr int WARPS_N = BN / WN;
    static_assert(WARPS_M * WARPS_N == 8, "8 warps");
    constexpr int MT = WM / 16;
    constexpr int NT = WN / 8;

    __shared__ __align__(16) float As[BM][BK + 4];   // stride 36: conflict-free frag reads
    __shared__ __align__(16) float Bs[BK][BN + 8];   // stride BN+8: conflict-free frag reads

    int z  = blockIdx.z;
    int zo = z / innerCount, zi = z % innerCount;
    const float* Ab = A + zo * aOuter + zi * aInner;
    const float* Bb = B + zo * bOuter + zi * bInner;
    float*       Cb = C + zo * cOuter + zi * cInner;
    const float* Rb = (EPI == 2 || EPI == 3) ? (res + zo * cOuter + zi * cInner) : nullptr;

    int m0 = blockIdx.y * BM;
    int n0 = blockIdx.x * BN;

    int tid  = threadIdx.x;
    int warp = tid >> 5, lane = tid & 31;
    int wm = (warp % WARPS_M) * WM;
    int wn = (warp / WARPS_M) * WN;
    int g  = lane >> 2, tc = lane & 3;

    float acc[MT][NT][4];
    #pragma unroll
    for (int i = 0; i < MT; i++)
        #pragma unroll
        for (int j = 0; j < NT; j++)
            #pragma unroll
            for (int e = 0; e < 4; e++) acc[i][j][e] = 0.f;

    for (int kt = 0; kt < K; kt += BK) {
        __syncthreads();
        // ---- load A tile (BM x 32), float4, k-contiguous ----
        #pragma unroll
        for (int i = 0; i < (BM * 8) / 256; ++i) {
            int idx = tid + i * 256;
            int m   = idx >> 3;
            int k4  = idx & 7;
            float4 t = *(const float4*)(Ab + (size_t)(m0 + m) * lda + kt + k4 * 4);
            *(float4*)&As[m][k4 * 4] =
                make_float4(to_tf32(t.x), to_tf32(t.y), to_tf32(t.z), to_tf32(t.w));
        }
        // ---- load B tile (32 x BN) ----
        if (!TRANSB) {
            #pragma unroll
            for (int i = 0; i < (BK * BN / 4) / 256; ++i) {
                int idx = tid + i * 256;
                int k   = idx / (BN / 4);
                int n4  = idx % (BN / 4);
                float4 t = *(const float4*)(Bb + (size_t)(kt + k) * ldb + n0 + n4 * 4);
                *(float4*)&Bs[k][n4 * 4] =
                    make_float4(to_tf32(t.x), to_tf32(t.y), to_tf32(t.z), to_tf32(t.w));
            }
        } else {
            #pragma unroll
            for (int i = 0; i < (BK * BN / 4) / 256; ++i) {
                int idx = tid + i * 256;
                int n   = idx >> 3;
                int k4  = idx & 7;
                float4 t = *(const float4*)(Bb + (size_t)(n0 + n) * ldb + kt + k4 * 4);
                Bs[k4 * 4 + 0][n] = to_tf32(t.x);
                Bs[k4 * 4 + 1][n] = to_tf32(t.y);
                Bs[k4 * 4 + 2][n] = to_tf32(t.z);
                Bs[k4 * 4 + 3][n] = to_tf32(t.w);
            }
        }
        __syncthreads();

        #pragma unroll
        for (int ks = 0; ks < BK / 8; ++ks) {
            uint32_t af[MT][4], bf[NT][2];
            #pragma unroll
            for (int mt = 0; mt < MT; ++mt) {
                int r = wm + mt * 16;
                af[mt][0] = __float_as_uint(As[r + g    ][ks * 8 + tc    ]);
                af[mt][1] = __float_as_uint(As[r + g + 8][ks * 8 + tc    ]);
                af[mt][2] = __float_as_uint(As[r + g    ][ks * 8 + tc + 4]);
                af[mt][3] = __float_as_uint(As[r + g + 8][ks * 8 + tc + 4]);
            }
            #pragma unroll
            for (int nt = 0; nt < NT; ++nt) {
                bf[nt][0] = __float_as_uint(Bs[ks * 8 + tc    ][wn + nt * 8 + g]);
                bf[nt][1] = __float_as_uint(Bs[ks * 8 + tc + 4][wn + nt * 8 + g]);
            }
            #pragma unroll
            for (int mt = 0; mt < MT; ++mt)
                #pragma unroll
                for (int nt = 0; nt < NT; ++nt)
                    mma_tf32(acc[mt][nt], af[mt], bf[nt]);
        }
    }

    // ---- epilogue ----
    #pragma unroll
    for (int mt = 0; mt < MT; ++mt) {
        #pragma unroll
        for (int nt = 0; nt < NT; ++nt) {
            int col = n0 + wn + nt * 8 + tc * 2;
            #pragma unroll
            for (int hrow = 0; hrow < 2; ++hrow) {
                int row  = m0 + wm + mt * 16 + g + hrow * 8;
                float v0 = acc[mt][nt][hrow * 2 + 0];
                float v1 = acc[mt][nt][hrow * 2 + 1];
                size_t off = (size_t)row * ldc + col;
                if (EPI == 1) {
                    v0 = gelu_tanh(v0 + bias[col]);
                    v1 = gelu_tanh(v1 + bias[col + 1]);
                } else if (EPI == 2) {
                    v0 = v0 + bias[col]     + Rb[off];
                    v1 = v1 + bias[col + 1] + Rb[off + 1];
                } else if (EPI == 3) {
                    v0 = 2.0f * v0 + Rb[off];
                    v1 = 2.0f * v1 + Rb[off + 1];
                }
                *(float2*)(Cb + off) = make_float2(v0, v1);
            }
        }
    }
}

// ---------------------------------------------------------------------------
// host launch
// ---------------------------------------------------------------------------
extern "C" void kernel_launch(void* const* d_in, const int* in_sizes, int n_in,
                              void* d_out, int out_size) {
    const float* x   = (const float*)d_in[0];
    const float* wq  = (const float*)d_in[1];
    const float* wk  = (const float*)d_in[2];
    const float* wv  = (const float*)d_in[3];
    const float* wo  = (const float*)d_in[4];
    const float* ln1 = (const float*)d_in[5];
    const float* ln2 = (const float*)d_in[6];
    const float* w1  = (const float*)d_in[7];
    const float* b1  = (const float*)d_in[8];
    const float* w2  = (const float*)d_in[9];
    const float* b2  = (const float*)d_in[10];
    float* out = (float*)d_out;

    float *c, *q, *k, *v, *s, *at, *x1, *x2, *h;
    cudaGetSymbolAddress((void**)&c,  g_c);
    cudaGetSymbolAddress((void**)&q,  g_q);
    cudaGetSymbolAddress((void**)&k,  g_k);
    cudaGetSymbolAddress((void**)&v,  g_v);
    cudaGetSymbolAddress((void**)&s,  g_s);
    cudaGetSymbolAddress((void**)&at, g_at);
    cudaGetSymbolAddress((void**)&x1, g_x1);
    cudaGetSymbolAddress((void**)&x2, g_x2);
    cudaGetSymbolAddress((void**)&h,  g_h);

    const long long rowStride = (long long)SEQ * DMODEL;   // per-batch stride in q/k/v/attn
    const long long sInner = (long long)SEQ * SEQ;
    const long long sOuter = (long long)NHEAD * SEQ * SEQ;

    // 1. c = LN1(x)
    ln_kernel<<<ROWS, 256>>>(x, ln1, c);

    // 2. q/k/v = c @ w{q,k,v}
    dim3 gA(DMODEL / 128, ROWS / 128, 1);                  // (8, 64)
    gemm_kernel<128,128,64,32,false,0><<<gA,256>>>(c,0,0,DMODEL, wq,0,0,DMODEL, q,0,0,DMODEL, nullptr,nullptr, ROWS,DMODEL,DMODEL, 1);
    gemm_kernel<128,128,64,32,false,0><<<gA,256>>>(c,0,0,DMODEL, wk,0,0,DMODEL, k,0,0,DMODEL, nullptr,nullptr, ROWS,DMODEL,DMODEL, 1);
    gemm_kernel<128,128,64,32,false,0><<<gA,256>>>(c,0,0,DMODEL, wv,0,0,DMODEL, v,0,0,DMODEL, nullptr,nullptr, ROWS,DMODEL,DMODEL, 1);

    // 3. s[b,h,i,j] = q_bh @ k_bh^T   (batched NT, 256 batches)
    dim3 gS(SEQ / 128, SEQ / 128, BATCH * NHEAD);          // (4, 4, 256)
    gemm_kernel<128,128,64,32,true,0><<<gS,256>>>(q,rowStride,HDIM,DMODEL, k,rowStride,HDIM,DMODEL, s,sOuter,sInner,SEQ, nullptr,nullptr, SEQ,SEQ,HDIM, NHEAD);

    // 4. softmax over j (scale 0.125 folded in)
    softmax_kernel<<<BATCH * NHEAD * SEQ, 256>>>(s);

    // 5. at_bh = p_bh @ v_bh   (batched NN, N=64)
    dim3 gPV(1, SEQ / 128, BATCH * NHEAD);                 // (1, 4, 256)
    gemm_kernel<128,64,32,32,false,0><<<gPV,256>>>(s,sOuter,sInner,SEQ, v,rowStride,HDIM,DMODEL, at,rowStride,HDIM,DMODEL, nullptr,nullptr, SEQ,HDIM,SEQ, NHEAD);

    // 6. x1 = x + 2*(at @ wo)
    gemm_kernel<128,128,64,32,false,3><<<gA,256>>>(at,0,0,DMODEL, wo,0,0,DMODEL, x1,0,0,DMODEL, nullptr, x, ROWS,DMODEL,DMODEL, 1);

    // 7-9. MLP #1: x2 = x1 + gelu(LN2(x1)@w1 + b1)@w2 + b2
    ln_kernel<<<ROWS, 256>>>(x1, ln2, c);
    dim3 gF(FFDIM / 128, ROWS / 128, 1);                   // (32, 64)
    gemm_kernel<128,128,64,32,false,1><<<gF,256>>>(c,0,0,DMODEL, w1,0,0,FFDIM, h,0,0,FFDIM, b1, nullptr, ROWS,FFDIM,DMODEL, 1);
    gemm_kernel<128,128,64,32,false,2><<<gA,256>>>(h,0,0,FFDIM, w2,0,0,DMODEL, x2,0,0,DMODEL, b2, x1, ROWS,DMODEL,FFDIM, 1);

    // 10-12. MLP #2: out = x2 + gelu(LN2(x2)@w1 + b1)@w2 + b2
    ln_kernel<<<ROWS, 256>>>(x2, ln2, c);
    gemm_kernel<128,128,64,32,false,1><<<gF,256>>>(c,0,0,DMODEL, w1,0,0,FFDIM, h,0,0,FFDIM, b1, nullptr, ROWS,FFDIM,DMODEL, 1);
    gemm_kernel<128,128,64,32,false,2><<<gA,256>>>(h,0,0,FFDIM, w2,0,0,DMODEL, out,0,0,DMODEL, b2, x2, ROWS,DMODEL,FFDIM, 1);
}

// round 2
// speedup vs baseline: 1.4228x; 1.4228x over previous
#include <cuda_runtime.h>
#include <math.h>
#include <stdint.h>

// ---------------------------------------------------------------------------
// Transformer block: B=16, S=512, D=1024, H=16, HD=64, FF=4096
// TF32 tensor-core GEMMs (mma.sync.m16n8k8) with 3-stage cp.async pipeline.
// ---------------------------------------------------------------------------

#define BATCH   16
#define SEQ     512
#define DMODEL  1024
#define NHEAD   16
#define HDIM    64
#define FFDIM   4096
#define ROWS    (BATCH * SEQ)          // 8192

__device__ float g_c  [ROWS * DMODEL];
__device__ float g_q  [ROWS * DMODEL];
__device__ float g_k  [ROWS * DMODEL];
__device__ float g_v  [ROWS * DMODEL];
__device__ float g_s  [(size_t)BATCH * NHEAD * SEQ * SEQ];   // 256 MB
__device__ float g_at [ROWS * DMODEL];
__device__ float g_x1 [ROWS * DMODEL];
__device__ float g_x2 [ROWS * DMODEL];
__device__ float g_h  [ROWS * FFDIM];                        // 128 MB

// ---------------------------------------------------------------------------
__device__ __forceinline__ uint32_t f2tf(float x) {
    float r;
    asm("cvt.rna.tf32.f32 %0, %1;" : "=f"(r) : "f"(x));
    return __float_as_uint(r);
}

__device__ __forceinline__ float gelu_tanh(float x) {
    float x3 = x * x * x;
    float u  = 0.7978845608028654f * (x + 0.044715f * x3);
    return 0.5f * x * (1.0f + tanhf(u));
}

__device__ __forceinline__ void mma_tf32(float* c, const uint32_t* a, const uint32_t* b) {
    asm volatile(
        "mma.sync.aligned.m16n8k8.row.col.f32.tf32.tf32.f32 "
        "{%0,%1,%2,%3}, {%4,%5,%6,%7}, {%8,%9}, {%0,%1,%2,%3};\n"
        : "+f"(c[0]), "+f"(c[1]), "+f"(c[2]), "+f"(c[3])
        : "r"(a[0]), "r"(a[1]), "r"(a[2]), "r"(a[3]),
          "r"(b[0]), "r"(b[1]));
}

__device__ __forceinline__ void cp16(uint32_t dst, const void* src) {
    asm volatile("cp.async.cg.shared.global [%0], [%1], 16;\n" :: "r"(dst), "l"(src));
}
__device__ __forceinline__ void cp4(uint32_t dst, const void* src) {
    asm volatile("cp.async.ca.shared.global [%0], [%1], 4;\n" :: "r"(dst), "l"(src));
}
__device__ __forceinline__ void cp_commit() {
    asm volatile("cp.async.commit_group;\n");
}
template<int N>
__device__ __forceinline__ void cp_wait() {
    asm volatile("cp.async.wait_group %0;\n" :: "n"(N));
}

// ---------------------------------------------------------------------------
// LayerNorm: one block per row of 1024
// ---------------------------------------------------------------------------
__global__ void ln_kernel(const float* __restrict__ x,
                          const float* __restrict__ scale,
                          float* __restrict__ out) {
    int row = blockIdx.x, tid = threadIdx.x;
    const float4* xr = (const float4*)(x + (size_t)row * DMODEL);
    float4 v = xr[tid];
    float s = v.x + v.y + v.z + v.w;
    float q = v.x * v.x + v.y * v.y + v.z * v.z + v.w * v.w;
    #pragma unroll
    for (int o = 16; o > 0; o >>= 1) {
        s += __shfl_xor_sync(0xffffffffu, s, o);
        q += __shfl_xor_sync(0xffffffffu, q, o);
    }
    __shared__ float ss[8], qq[8];
    if ((tid & 31) == 0) { ss[tid >> 5] = s; qq[tid >> 5] = q; }
    __syncthreads();
    if (tid == 0) {
        float ts = 0.f, tq = 0.f;
        #pragma unroll
        for (int i = 0; i < 8; i++) { ts += ss[i]; tq += qq[i]; }
        ss[0] = ts; qq[0] = tq;
    }
    __syncthreads();
    float mean = ss[0] * (1.0f / DMODEL);
    float var  = qq[0] * (1.0f / DMODEL) - mean * mean;
    float r    = rsqrtf(var + 1e-6f);
    float4 sc  = ((const float4*)scale)[tid];
    float4 o;
    o.x = (v.x - mean) * r * sc.x;
    o.y = (v.y - mean) * r * sc.y;
    o.z = (v.z - mean) * r * sc.z;
    o.w = (v.w - mean) * r * sc.w;
    ((float4*)(out + (size_t)row * DMODEL))[tid] = o;
}

// ---------------------------------------------------------------------------
// Softmax over rows of 512 (in-place), with 1/sqrt(HD)=0.125 pre-scale
// ---------------------------------------------------------------------------
__global__ void softmax_kernel(float* __restrict__ s) {
    size_t row = blockIdx.x;
    float2* p = (float2*)(s + row * SEQ);
    int tid = threadIdx.x;
    float2 v = p[tid];
    v.x *= 0.125f; v.y *= 0.125f;
    float m = fmaxf(v.x, v.y);
    #pragma unroll
    for (int o = 16; o > 0; o >>= 1) m = fmaxf(m, __shfl_xor_sync(0xffffffffu, m, o));
    __shared__ float rm[8], rs[8];
    if ((tid & 31) == 0) rm[tid >> 5] = m;
    __syncthreads();
    if (tid == 0) {
        float t = rm[0];
        #pragma unroll
        for (int i = 1; i < 8; i++) t = fmaxf(t, rm[i]);
        rm[0] = t;
    }
    __syncthreads();
    m = rm[0];
    float e0 = __expf(v.x - m), e1 = __expf(v.y - m);
    float sum = e0 + e1;
    #pragma unroll
    for (int o = 16; o > 0; o >>= 1) sum += __shfl_xor_sync(0xffffffffu, sum, o);
    if ((tid & 31) == 0) rs[tid >> 5] = sum;
    __syncthreads();
    if (tid == 0) {
        float t = 0.f;
        #pragma unroll
        for (int i = 0; i < 8; i++) t += rs[i];
        rs[0] = t;
    }
    __syncthreads();
    float inv = 1.0f / rs[0];
    p[tid] = make_float2(e0 * inv, e1 * inv);
}

// ---------------------------------------------------------------------------
// Generic batched TF32 GEMM with 3-stage cp.async pipeline.
// C[M,N] = A[M,K] * B[K,N]   (A row-major)
// TRANSB=false: B[k,n] = Bptr[k*ldb + n]
// TRANSB=true : B[k,n] = Bptr[n*ldb + k]    (NT, for Q@K^T)
// EPI: 0 none | 1 gelu(acc+bias) | 2 acc+bias+res | 3 res+2*acc
// ---------------------------------------------------------------------------
template<int BM, int BN, int WM, int WN, bool TRANSB, int EPI>
__global__ void __launch_bounds__(256, 2)
gemm_kernel(const float* __restrict__ A, long long aOuter, long long aInner, int lda,
            const float* __restrict__ B, long long bOuter, long long bInner, int ldb,
            float* __restrict__ C, long long cOuter, long long cInner, int ldc,
            const float* __restrict__ bias,
            const float* __restrict__ res,
            int M, int N, int K, int innerCount) {
    constexpr int BK = 32;
    constexpr int NSTAGES = 3;
    constexpr int WARPS_M = BM / WM;
    constexpr int WARPS_N = BN / WN;
    static_assert(WARPS_M * WARPS_N == 8, "8 warps");
    constexpr int MT = WM / 16;
    constexpr int NT = WN / 8;
    constexpr int ASTRIDE = BK + 4;            // 36 floats
    constexpr int BSTRIDE = BN + 8;
    constexpr int A_F = BM * ASTRIDE;
    constexpr int B_F = BK * BSTRIDE;
    constexpr int STAGE_F = A_F + B_F;

    extern __shared__ float smem[];
    uint32_t smem_u32 = (uint32_t)__cvta_generic_to_shared(smem);

    int z  = blockIdx.z;
    int zo = z / innerCount, zi = z % innerCount;
    const float* Ab = A + zo * aOuter + zi * aInner;
    const float* Bb = B + zo * bOuter + zi * bInner;
    float*       Cb = C + zo * cOuter + zi * cInner;
    const float* Rb = (EPI == 2 || EPI == 3) ? (res + zo * cOuter + zi * cInner) : nullptr;

    int m0 = blockIdx.y * BM;
    int n0 = blockIdx.x * BN;

    int tid  = threadIdx.x;
    int warp = tid >> 5, lane = tid & 31;
    int wm = (warp % WARPS_M) * WM;
    int wn = (warp / WARPS_M) * WN;
    int g  = lane >> 2, tc = lane & 3;

    // precomputed load indices
    int a_m  = tid >> 3;            // 0..31 base (stride 32 per iter)
    int a_k4 = tid & 7;
    int b_k  = tid / (BN / 4);
    int b_n4 = tid % (BN / 4);
    int bt_n  = tid >> 3;
    int bt_k4 = tid & 7;

    float acc[MT][NT][4];
    #pragma unroll
    for (int i = 0; i < MT; i++)
        #pragma unroll
        for (int j = 0; j < NT; j++)
            #pragma unroll
            for (int e = 0; e < 4; e++) acc[i][j][e] = 0.f;

    const int ntiles = K / BK;

    // tile loader: loads tile t (k offset t*BK) into stage s
    auto load_tile = [&](int t, int s) {
        int kt = t * BK;
        uint32_t aBase = smem_u32 + (uint32_t)(s * STAGE_F) * 4u;
        uint32_t bBase = aBase + (uint32_t)A_F * 4u;
        #pragma unroll
        for (int i = 0; i < (BM * 8) / 256; ++i) {
            int m = a_m + i * 32;
            cp16(aBase + (uint32_t)(m * ASTRIDE + a_k4 * 4) * 4u,
                 Ab + (size_t)(m0 + m) * lda + kt + a_k4 * 4);
        }
        if (!TRANSB) {
            #pragma unroll
            for (int i = 0; i < (BK * BN / 4) / 256; ++i) {
                int k = b_k + i * (256 / (BN / 4));
                cp16(bBase + (uint32_t)(k * BSTRIDE + b_n4 * 4) * 4u,
                     Bb + (size_t)(kt + k) * ldb + n0 + b_n4 * 4);
            }
        } else {
            #pragma unroll
            for (int i = 0; i < (BN * 8) / 256; ++i) {
                int n = bt_n + i * 32;
                const float* src = Bb + (size_t)(n0 + n) * ldb + kt + bt_k4 * 4;
                #pragma unroll
                for (int e = 0; e < 4; ++e)
                    cp4(bBase + (uint32_t)((bt_k4 * 4 + e) * BSTRIDE + n) * 4u, src + e);
            }
        }
    };

    // prologue: preload NSTAGES-1 tiles
    #pragma unroll
    for (int s = 0; s < NSTAGES - 1; ++s) {
        if (s < ntiles) load_tile(s, s);
        cp_commit();
    }

    for (int t = 0; t < ntiles; ++t) {
        cp_wait<NSTAGES - 2>();
        __syncthreads();

        // issue loads for tile t + NSTAGES-1 (writes buffer computed at t-1)
        int tn = t + NSTAGES - 1;
        if (tn < ntiles) load_tile(tn, tn % NSTAGES);
        cp_commit();

        int cur = t % NSTAGES;
        const float* Asc = smem + cur * STAGE_F;
        const float* Bsc = Asc + A_F;

        #pragma unroll
        for (int ks = 0; ks < BK / 8; ++ks) {
            uint32_t af[MT][4], bf[NT][2];
            #pragma unroll
            for (int mt = 0; mt < MT; ++mt) {
                int r = wm + mt * 16;
                af[mt][0] = f2tf(Asc[(r + g    ) * ASTRIDE + ks * 8 + tc    ]);
                af[mt][1] = f2tf(Asc[(r + g + 8) * ASTRIDE + ks * 8 + tc    ]);
                af[mt][2] = f2tf(Asc[(r + g    ) * ASTRIDE + ks * 8 + tc + 4]);
                af[mt][3] = f2tf(Asc[(r + g + 8) * ASTRIDE + ks * 8 + tc + 4]);
            }
            #pragma unroll
            for (int nt = 0; nt < NT; ++nt) {
                bf[nt][0] = f2tf(Bsc[(ks * 8 + tc    ) * BSTRIDE + wn + nt * 8 + g]);
                bf[nt][1] = f2tf(Bsc[(ks * 8 + tc + 4) * BSTRIDE + wn + nt * 8 + g]);
            }
            #pragma unroll
            for (int mt = 0; mt < MT; ++mt)
                #pragma unroll
                for (int nt = 0; nt < NT; ++nt)
                    mma_tf32(acc[mt][nt], af[mt], bf[nt]);
        }
    }

    // ---- epilogue ----
    #pragma unroll
    for (int mt = 0; mt < MT; ++mt) {
        #pragma unroll
        for (int nt = 0; nt < NT; ++nt) {
            int col = n0 + wn + nt * 8 + tc * 2;
            #pragma unroll
            for (int hrow = 0; hrow < 2; ++hrow) {
                int row  = m0 + wm + mt * 16 + g + hrow * 8;
                float v0 = acc[mt][nt][hrow * 2 + 0];
                float v1 = acc[mt][nt][hrow * 2 + 1];
                size_t off = (size_t)row * ldc + col;
                if (EPI == 1) {
                    v0 = gelu_tanh(v0 + bias[col]);
                    v1 = gelu_tanh(v1 + bias[col + 1]);
                } else if (EPI == 2) {
                    v0 = v0 + bias[col]     + Rb[off];
                    v1 = v1 + bias[col + 1] + Rb[off + 1];
                } else if (EPI == 3) {
                    v0 = 2.0f * v0 + Rb[off];
                    v1 = 2.0f * v1 + Rb[off + 1];
                }
                *(float2*)(Cb + off) = make_float2(v0, v1);
            }
        }
    }
}

// ---------------------------------------------------------------------------
// host launch
// ---------------------------------------------------------------------------
static inline int stage_bytes(int BN) {
    return (128 * 36 + 32 * (BN + 8)) * 3 * 4;
}

extern "C" void kernel_launch(void* const* d_in, const int* in_sizes, int n_in,
                              void* d_out, int out_size) {
    const float* x   = (const float*)d_in[0];
    const float* wq  = (const float*)d_in[1];
    const float* wk  = (const float*)d_in[2];
    const float* wv  = (const float*)d_in[3];
    const float* wo  = (const float*)d_in[4];
    const float* ln1 = (const float*)d_in[5];
    const float* ln2 = (const float*)d_in[6];
    const float* w1  = (const float*)d_in[7];
    const float* b1  = (const float*)d_in[8];
    const float* w2  = (const float*)d_in[9];
    const float* b2  = (const float*)d_in[10];
    float* out = (float*)d_out;

    float *c, *q, *k, *v, *s, *at, *x1, *x2, *h;
    cudaGetSymbolAddress((void**)&c,  g_c);
    cudaGetSymbolAddress((void**)&q,  g_q);
    cudaGetSymbolAddress((void**)&k,  g_k);
    cudaGetSymbolAddress((void**)&v,  g_v);
    cudaGetSymbolAddress((void**)&s,  g_s);
    cudaGetSymbolAddress((void**)&at, g_at);
    cudaGetSymbolAddress((void**)&x1, g_x1);
    cudaGetSymbolAddress((void**)&x2, g_x2);
    cudaGetSymbolAddress((void**)&h,  g_h);

    const int SM128 = stage_bytes(128);   // 107520
    const int SM64  = stage_bytes(64);    //  82944

    static bool attr_done = false;
    if (!attr_done) {
        cudaFuncSetAttribute(gemm_kernel<128,128,64,32,false,0>, cudaFuncAttributeMaxDynamicSharedMemorySize, SM128);
        cudaFuncSetAttribute(gemm_kernel<128,128,64,32,true, 0>, cudaFuncAttributeMaxDynamicSharedMemorySize, SM128);
        cudaFuncSetAttribute(gemm_kernel<128, 64,32,32,false,0>, cudaFuncAttributeMaxDynamicSharedMemorySize, SM64);
        cudaFuncSetAttribute(gemm_kernel<128,128,64,32,false,1>, cudaFuncAttributeMaxDynamicSharedMemorySize, SM128);
        cudaFuncSetAttribute(gemm_kernel<128,128,64,32,false,2>, cudaFuncAttributeMaxDynamicSharedMemorySize, SM128);
        cudaFuncSetAttribute(gemm_kernel<128,128,64,32,false,3>, cudaFuncAttributeMaxDynamicSharedMemorySize, SM128);
        attr_done = true;
    }

    const long long rowStride = (long long)SEQ * DMODEL;
    const long long sInner = (long long)SEQ * SEQ;
    const long long sOuter = (long long)NHEAD * SEQ * SEQ;

    // 1. c = LN1(x)
    ln_kernel<<<ROWS, 256>>>(x, ln1, c);

    // 2. q/k/v = c @ w{q,k,v}
    dim3 gA(DMODEL / 128, ROWS / 128, 1);
    gemm_kernel<128,128,64,32,false,0><<<gA,256,SM128>>>(c,0,0,DMODEL, wq,0,0,DMODEL, q,0,0,DMODEL, nullptr,nullptr, ROWS,DMODEL,DMODEL, 1);
    gemm_kernel<128,128,64,32,false,0><<<gA,256,SM128>>>(c,0,0,DMODEL, wk,0,0,DMODEL, k,0,0,DMODEL, nullptr,nullptr, ROWS,DMODEL,DMODEL, 1);
    gemm_kernel<128,128,64,32,false,0><<<gA,256,SM128>>>(c,0,0,DMODEL, wv,0,0,DMODEL, v,0,0,DMODEL, nullptr,nullptr, ROWS,DMODEL,DMODEL, 1);

    // 3. s[b,h,i,j] = q_bh @ k_bh^T
    dim3 gS(SEQ / 128, SEQ / 128, BATCH * NHEAD);
    gemm_kernel<128,128,64,32,true,0><<<gS,256,SM128>>>(q,rowStride,HDIM,DMODEL, k,rowStride,HDIM,DMODEL, s,sOuter,sInner,SEQ, nullptr,nullptr, SEQ,SEQ,HDIM, NHEAD);

    // 4. softmax over j
    softmax_kernel<<<BATCH * NHEAD * SEQ, 256>>>(s);

    // 5. at_bh = p_bh @ v_bh
    dim3 gPV(1, SEQ / 128, BATCH * NHEAD);
    gemm_kernel<128,64,32,32,false,0><<<gPV,256,SM64>>>(s,sOuter,sInner,SEQ, v,rowStride,HDIM,DMODEL, at,rowStride,HDIM,DMODEL, nullptr,nullptr, SEQ,HDIM,SEQ, NHEAD);

    // 6. x1 = x + 2*(at @ wo)
    gemm_kernel<128,128,64,32,false,3><<<gA,256,SM128>>>(at,0,0,DMODEL, wo,0,0,DMODEL, x1,0,0,DMODEL, nullptr, x, ROWS,DMODEL,DMODEL, 1);

    // 7-9. MLP #1
    ln_kernel<<<ROWS, 256>>>(x1, ln2, c);
    dim3 gF(FFDIM / 128, ROWS / 128, 1);
    gemm_kernel<128,128,64,32,false,1><<<gF,256,SM128>>>(c,0,0,DMODEL, w1,0,0,FFDIM, h,0,0,FFDIM, b1, nullptr, ROWS,FFDIM,DMODEL, 1);
    gemm_kernel<128,128,64,32,false,2><<<gA,256,SM128>>>(h,0,0,FFDIM, w2,0,0,DMODEL, x2,0,0,DMODEL, b2, x1, ROWS,DMODEL,FFDIM, 1);

    // 10-12. MLP #2
    ln_kernel<<<ROWS, 256>>>(x2, ln2, c);
    gemm_kernel<128,128,64,32,false,1><<<gF,256,SM128>>>(c,0,0,DMODEL, w1,0,0,FFDIM, h,0,0,FFDIM, b1, nullptr, ROWS,FFDIM,DMODEL, 1);
    gemm_kernel<128,128,64,32,false,2><<<gA,256,SM128>>>(h,0,0,FFDIM, w2,0,0,DMODEL, out,0,0,DMODEL, b2, x2, ROWS,DMODEL,FFDIM, 1);
}

// round 3
// speedup vs baseline: 1.5400x; 1.0824x over previous
#include <cuda_runtime.h>
#include <math.h>
#include <stdint.h>

// ---------------------------------------------------------------------------
// Transformer block: B=16, S=512, D=1024, H=16, HD=64, FF=4096
// TF32 tensor-core GEMMs, 3-stage cp.async pipeline, pre-rounded operands
// (no cvt in mainloop), B operands K-contiguous ([n][k]).
// ---------------------------------------------------------------------------

#define BATCH   16
#define SEQ     512
#define DMODEL  1024
#define NHEAD   16
#define HDIM    64
#define FFDIM   4096
#define ROWS    (BATCH * SEQ)          // 8192

__device__ float g_c  [ROWS * DMODEL];
__device__ float g_q  [ROWS * DMODEL];
__device__ float g_k  [ROWS * DMODEL];
__device__ float g_v  [ROWS * DMODEL];
__device__ float g_vT [ROWS * DMODEL];                       // [b,h][d][j]
__device__ float g_s  [(size_t)BATCH * NHEAD * SEQ * SEQ];   // 256 MB
__device__ float g_at [ROWS * DMODEL];
__device__ float g_x1 [ROWS * DMODEL];
__device__ float g_x2 [ROWS * DMODEL];
__device__ float g_h  [ROWS * FFDIM];                        // 128 MB
// transposed + tf32-rounded weights
__device__ float g_wqT[DMODEL * DMODEL];
__device__ float g_wkT[DMODEL * DMODEL];
__device__ float g_wvT[DMODEL * DMODEL];
__device__ float g_woT[DMODEL * DMODEL];
__device__ float g_w1T[(size_t)DMODEL * FFDIM];
__device__ float g_w2T[(size_t)DMODEL * FFDIM];

// ---------------------------------------------------------------------------
__device__ __forceinline__ float tf32r(float x) {
    float r;
    asm("cvt.rna.tf32.f32 %0, %1;" : "=f"(r) : "f"(x));
    return r;
}

__device__ __forceinline__ float gelu_tanh(float x) {
    float x3 = x * x * x;
    float u  = 0.7978845608028654f * (x + 0.044715f * x3);
    return 0.5f * x * (1.0f + tanhf(u));
}

__device__ __forceinline__ void mma_tf32(float* c, const uint32_t* a, const uint32_t* b) {
    asm volatile(
        "mma.sync.aligned.m16n8k8.row.col.f32.tf32.tf32.f32 "
        "{%0,%1,%2,%3}, {%4,%5,%6,%7}, {%8,%9}, {%0,%1,%2,%3};\n"
        : "+f"(c[0]), "+f"(c[1]), "+f"(c[2]), "+f"(c[3])
        : "r"(a[0]), "r"(a[1]), "r"(a[2]), "r"(a[3]),
          "r"(b[0]), "r"(b[1]));
}

__device__ __forceinline__ void cp16(uint32_t dst, const void* src) {
    asm volatile("cp.async.cg.shared.global [%0], [%1], 16;\n" :: "r"(dst), "l"(src));
}
__device__ __forceinline__ void cp_commit() {
    asm volatile("cp.async.commit_group;\n");
}
template<int N>
__device__ __forceinline__ void cp_wait() {
    asm volatile("cp.async.wait_group %0;\n" :: "n"(N));
}

// ---------------------------------------------------------------------------
// Batched transpose + tf32 round:  out[z][c][r] = rnd(in[z][r][c])
// z offset: (z/ic)*outer + (z%ic)*inner  (both matrices)
// ---------------------------------------------------------------------------
__global__ void transpose_rnd(const float* __restrict__ in, long long iOuter, long long iInner, int ldin,
                              float* __restrict__ out, long long oOuter, long long oInner, int ldout,
                              int R, int C, int ic) {
    __shared__ float t[32][33];
    int z = blockIdx.z;
    const float* ib = in  + (z / ic) * iOuter + (z % ic) * iInner;
    float*       ob = out + (z / ic) * oOuter + (z % ic) * oInner;
    int r0 = blockIdx.y * 32, c0 = blockIdx.x * 32;
    #pragma unroll
    for (int j = 0; j < 32; j += 8)
        t[threadIdx.y + j][threadIdx.x] = ib[(size_t)(r0 + threadIdx.y + j) * ldin + c0 + threadIdx.x];
    __syncthreads();
    #pragma unroll
    for (int j = 0; j < 32; j += 8)
        ob[(size_t)(c0 + threadIdx.y + j) * ldout + r0 + threadIdx.x] =
            tf32r(t[threadIdx.x][threadIdx.y + j]);
}

// ---------------------------------------------------------------------------
// LayerNorm: one block per row of 1024 (output tf32-rounded)
// ---------------------------------------------------------------------------
__global__ void ln_kernel(const float* __restrict__ x,
                          const float* __restrict__ scale,
                          float* __restrict__ out) {
    int row = blockIdx.x, tid = threadIdx.x;
    const float4* xr = (const float4*)(x + (size_t)row * DMODEL);
    float4 v = xr[tid];
    float s = v.x + v.y + v.z + v.w;
    float q = v.x * v.x + v.y * v.y + v.z * v.z + v.w * v.w;
    #pragma unroll
    for (int o = 16; o > 0; o >>= 1) {
        s += __shfl_xor_sync(0xffffffffu, s, o);
        q += __shfl_xor_sync(0xffffffffu, q, o);
    }
    __shared__ float ss[8], qq[8];
    if ((tid & 31) == 0) { ss[tid >> 5] = s; qq[tid >> 5] = q; }
    __syncthreads();
    if (tid == 0) {
        float ts = 0.f, tq = 0.f;
        #pragma unroll
        for (int i = 0; i < 8; i++) { ts += ss[i]; tq += qq[i]; }
        ss[0] = ts; qq[0] = tq;
    }
    __syncthreads();
    float mean = ss[0] * (1.0f / DMODEL);
    float var  = qq[0] * (1.0f / DMODEL) - mean * mean;
    float r    = rsqrtf(var + 1e-6f);
    float4 sc  = ((const float4*)scale)[tid];
    float4 o;
    o.x = tf32r((v.x - mean) * r * sc.x);
    o.y = tf32r((v.y - mean) * r * sc.y);
    o.z = tf32r((v.z - mean) * r * sc.z);
    o.w = tf32r((v.w - mean) * r * sc.w);
    ((float4*)(out + (size_t)row * DMODEL))[tid] = o;
}

// ---------------------------------------------------------------------------
// Softmax over rows of 512 (in-place), 0.125 pre-scale, tf32-rounded output
// ---------------------------------------------------------------------------
__global__ void softmax_kernel(float* __restrict__ s) {
    size_t row = blockIdx.x;
    float2* p = (float2*)(s + row * SEQ);
    int tid = threadIdx.x;
    float2 v = p[tid];
    v.x *= 0.125f; v.y *= 0.125f;
    float m = fmaxf(v.x, v.y);
    #pragma unroll
    for (int o = 16; o > 0; o >>= 1) m = fmaxf(m, __shfl_xor_sync(0xffffffffu, m, o));
    __shared__ float rm[8], rs[8];
    if ((tid & 31) == 0) rm[tid >> 5] = m;
    __syncthreads();
    if (tid == 0) {
        float t = rm[0];
        #pragma unroll
        for (int i = 1; i < 8; i++) t = fmaxf(t, rm[i]);
        rm[0] = t;
    }
    __syncthreads();
    m = rm[0];
    float e0 = __expf(v.x - m), e1 = __expf(v.y - m);
    float sum = e0 + e1;
    #pragma unroll
    for (int o = 16; o > 0; o >>= 1) sum += __shfl_xor_sync(0xffffffffu, sum, o);
    if ((tid & 31) == 0) rs[tid >> 5] = sum;
    __syncthreads();
    if (tid == 0) {
        float t = 0.f;
        #pragma unroll
        for (int i = 0; i < 8; i++) t += rs[i];
        rs[0] = t;
    }
    __syncthreads();
    float inv = 1.0f / rs[0];
    p[tid] = make_float2(tf32r(e0 * inv), tf32r(e1 * inv));
}

// ---------------------------------------------------------------------------
// Batched TF32 GEMM, 3-stage cp.async pipeline.
// C[M,N] = A[M,K] * B^T where Bptr is [N,K] row-major (K contiguous).
// All operands must be pre-rounded to tf32.
// EPI: 0 none | 1 gelu(acc+bias) | 2 acc+bias+res | 3 res+2*acc
// RND: round outputs to tf32 (for GEMM-feeding intermediates)
// ---------------------------------------------------------------------------
template<int BM, int BN, int WM, int WN, int EPI, bool RND>
__global__ void __launch_bounds__(256, 2)
gemm_kernel(const float* __restrict__ A, long long aOuter, long long aInner, int lda,
            const float* __restrict__ B, long long bOuter, long long bInner, int ldb,
            float* __restrict__ C, long long cOuter, long long cInner, int ldc,
            const float* __restrict__ bias,
            const float* __restrict__ res,
            int M, int N, int K, int innerCount) {
    constexpr int BK = 32;
    constexpr int NSTAGES = 3;
    constexpr int WARPS_M = BM / WM;
    constexpr int WARPS_N = BN / WN;
    static_assert(WARPS_M * WARPS_N == 8, "8 warps");
    constexpr int MT = WM / 16;
    constexpr int NT = WN / 8;
    constexpr int ASTRIDE = BK + 4;            // 36 floats
    constexpr int BSTRIDE = BK + 4;            // B stored [n][k]
    constexpr int A_F = BM * ASTRIDE;
    constexpr int B_F = BN * BSTRIDE;
    constexpr int STAGE_F = A_F + B_F;

    extern __shared__ float smem[];
    uint32_t smem_u32 = (uint32_t)__cvta_generic_to_shared(smem);

    int z  = blockIdx.z;
    int zo = z / innerCount, zi = z % innerCount;
    const float* Ab = A + zo * aOuter + zi * aInner;
    const float* Bb = B + zo * bOuter + zi * bInner;
    float*       Cb = C + zo * cOuter + zi * cInner;
    const float* Rb = (EPI == 2 || EPI == 3) ? (res + zo * cOuter + zi * cInner) : nullptr;

    int m0 = blockIdx.y * BM;
    int n0 = blockIdx.x * BN;

    int tid  = threadIdx.x;
    int warp = tid >> 5, lane = tid & 31;
    int wm = (warp % WARPS_M) * WM;
    int wn = (warp / WARPS_M) * WN;
    int g  = lane >> 2, tc = lane & 3;

    // loader indices (identical pattern for A and B: row-major, K contiguous)
    int l_r  = tid >> 3;            // 0..31 base (stride 32)
    int l_k4 = tid & 7;

    const float* Aptr = Ab + (size_t)(m0 + l_r) * lda + l_k4 * 4;
    const float* Bptr = Bb + (size_t)(n0 + l_r) * ldb + l_k4 * 4;

    float acc[MT][NT][4];
    #pragma unroll
    for (int i = 0; i < MT; i++)
        #pragma unroll
        for (int j = 0; j < NT; j++)
            #pragma unroll
            for (int e = 0; e < 4; e++) acc[i][j][e] = 0.f;

    const int ntiles = K / BK;

    auto load_tile = [&](int t, int s) {
        int kt = t * BK;
        uint32_t aBase = smem_u32 + (uint32_t)(s * STAGE_F) * 4u;
        uint32_t bBase = aBase + (uint32_t)A_F * 4u;
        #pragma unroll
        for (int i = 0; i < BM / 32; ++i)
            cp16(aBase + (uint32_t)((l_r + i * 32) * ASTRIDE + l_k4 * 4) * 4u,
                 Aptr + (size_t)(i * 32) * lda + kt);
        #pragma unroll
        for (int i = 0; i < BN / 32; ++i)
            cp16(bBase + (uint32_t)((l_r + i * 32) * BSTRIDE + l_k4 * 4) * 4u,
                 Bptr + (size_t)(i * 32) * ldb + kt);
    };

    #pragma unroll
    for (int s = 0; s < NSTAGES - 1; ++s) {
        if (s < ntiles) load_tile(s, s);
        cp_commit();
    }

    for (int t = 0; t < ntiles; ++t) {
        cp_wait<NSTAGES - 2>();
        __syncthreads();

        int tn = t + NSTAGES - 1;
        if (tn < ntiles) load_tile(tn, tn % NSTAGES);
        cp_commit();

        int cur = t % NSTAGES;
        const float* Asc = smem + cur * STAGE_F;
        const float* Bsc = Asc + A_F;

        #pragma unroll
        for (int ks = 0; ks < BK / 8; ++ks) {
            uint32_t af[MT][4], bf[NT][2];
            #pragma unroll
            for (int mt = 0; mt < MT; ++mt) {
                int r = wm + mt * 16;
                af[mt][0] = __float_as_uint(Asc[(r + g    ) * ASTRIDE + ks * 8 + tc    ]);
                af[mt][1] = __float_as_uint(Asc[(r + g + 8) * ASTRIDE + ks * 8 + tc    ]);
                af[mt][2] = __float_as_uint(Asc[(r + g    ) * ASTRIDE + ks * 8 + tc + 4]);
                af[mt][3] = __float_as_uint(Asc[(r + g + 8) * ASTRIDE + ks * 8 + tc + 4]);
            }
            #pragma unroll
            for (int nt = 0; nt < NT; ++nt) {
                int n = wn + nt * 8 + g;
                bf[nt][0] = __float_as_uint(Bsc[n * BSTRIDE + ks * 8 + tc    ]);
                bf[nt][1] = __float_as_uint(Bsc[n * BSTRIDE + ks * 8 + tc + 4]);
            }
            #pragma unroll
            for (int mt = 0; mt < MT; ++mt)
                #pragma unroll
                for (int nt = 0; nt < NT; ++nt)
                    mma_tf32(acc[mt][nt], af[mt], bf[nt]);
        }
    }

    // ---- epilogue ----
    #pragma unroll
    for (int mt = 0; mt < MT; ++mt) {
        #pragma unroll
        for (int nt = 0; nt < NT; ++nt) {
            int col = n0 + wn + nt * 8 + tc * 2;
            #pragma unroll
            for (int hrow = 0; hrow < 2; ++hrow) {
                int row  = m0 + wm + mt * 16 + g + hrow * 8;
                float v0 = acc[mt][nt][hrow * 2 + 0];
                float v1 = acc[mt][nt][hrow * 2 + 1];
                size_t off = (size_t)row * ldc + col;
                if (EPI == 1) {
                    v0 = gelu_tanh(v0 + bias[col]);
                    v1 = gelu_tanh(v1 + bias[col + 1]);
                } else if (EPI == 2) {
                    v0 = v0 + bias[col]     + Rb[off];
                    v1 = v1 + bias[col + 1] + Rb[off + 1];
                } else if (EPI == 3) {
                    v0 = 2.0f * v0 + Rb[off];
                    v1 = 2.0f * v1 + Rb[off + 1];
                }
                if (RND) { v0 = tf32r(v0); v1 = tf32r(v1); }
                *(float2*)(Cb + off) = make_float2(v0, v1);
            }
        }
    }
}

// ---------------------------------------------------------------------------
// host launch
// ---------------------------------------------------------------------------
extern "C" void kernel_launch(void* const* d_in, const int* in_sizes, int n_in,
                              void* d_out, int out_size) {
    const float* x   = (const float*)d_in[0];
    const float* wq  = (const float*)d_in[1];
    const float* wk  = (const float*)d_in[2];
    const float* wv  = (const float*)d_in[3];
    const float* wo  = (const float*)d_in[4];
    const float* ln1 = (const float*)d_in[5];
    const float* ln2 = (const float*)d_in[6];
    const float* w1  = (const float*)d_in[7];
    const float* b1  = (const float*)d_in[8];
    const float* w2  = (const float*)d_in[9];
    const float* b2  = (const float*)d_in[10];
    float* out = (float*)d_out;

    float *c, *q, *k, *v, *vT, *s, *at, *x1, *x2, *h;
    float *wqT, *wkT, *wvT, *woT, *w1T, *w2T;
    cudaGetSymbolAddress((void**)&c,  g_c);
    cudaGetSymbolAddress((void**)&q,  g_q);
    cudaGetSymbolAddress((void**)&k,  g_k);
    cudaGetSymbolAddress((void**)&v,  g_v);
    cudaGetSymbolAddress((void**)&vT, g_vT);
    cudaGetSymbolAddress((void**)&s,  g_s);
    cudaGetSymbolAddress((void**)&at, g_at);
    cudaGetSymbolAddress((void**)&x1, g_x1);
    cudaGetSymbolAddress((void**)&x2, g_x2);
    cudaGetSymbolAddress((void**)&h,  g_h);
    cudaGetSymbolAddress((void**)&wqT, g_wqT);
    cudaGetSymbolAddress((void**)&wkT, g_wkT);
    cudaGetSymbolAddress((void**)&wvT, g_wvT);
    cudaGetSymbolAddress((void**)&woT, g_woT);
    cudaGetSymbolAddress((void**)&w1T, g_w1T);
    cudaGetSymbolAddress((void**)&w2T, g_w2T);

    constexpr int STG = 3 * 4;
    const int SM128 = (128 * 36 + 128 * 36) * STG;   // 110592
    const int SM64  = (128 * 36 +  64 * 36) * STG;   //  82944

    static bool attr_done = false;
    if (!attr_done) {
        cudaFuncSetAttribute(gemm_kernel<128,128,64,32,0,true >, cudaFuncAttributeMaxDynamicSharedMemorySize, SM128);
        cudaFuncSetAttribute(gemm_kernel<128,128,64,32,0,false>, cudaFuncAttributeMaxDynamicSharedMemorySize, SM128);
        cudaFuncSetAttribute(gemm_kernel<128, 64,32,32,0,true >, cudaFuncAttributeMaxDynamicSharedMemorySize, SM64);
        cudaFuncSetAttribute(gemm_kernel<128,128,64,32,1,true >, cudaFuncAttributeMaxDynamicSharedMemorySize, SM128);
        cudaFuncSetAttribute(gemm_kernel<128,128,64,32,2,false>, cudaFuncAttributeMaxDynamicSharedMemorySize, SM128);
        cudaFuncSetAttribute(gemm_kernel<128,128,64,32,3,false>, cudaFuncAttributeMaxDynamicSharedMemorySize, SM128);
        attr_done = true;
    }

    const long long rowStride = (long long)SEQ * DMODEL;
    const long long sInner = (long long)SEQ * SEQ;
    const long long sOuter = (long long)NHEAD * SEQ * SEQ;
    const long long vTb = (long long)NHEAD * HDIM * SEQ;   // per-batch stride in vT
    const long long vTh = (long long)HDIM * SEQ;           // per-head stride in vT

    dim3 tb(32, 8);

    // 0. weight prep: transpose + tf32-round
    transpose_rnd<<<dim3(DMODEL/32, DMODEL/32, 1), tb>>>(wq,0,0,DMODEL, wqT,0,0,DMODEL, DMODEL,DMODEL, 1);
    transpose_rnd<<<dim3(DMODEL/32, DMODEL/32, 1), tb>>>(wk,0,0,DMODEL, wkT,0,0,DMODEL, DMODEL,DMODEL, 1);
    transpose_rnd<<<dim3(DMODEL/32, DMODEL/32, 1), tb>>>(wv,0,0,DMODEL, wvT,0,0,DMODEL, DMODEL,DMODEL, 1);
    transpose_rnd<<<dim3(DMODEL/32, DMODEL/32, 1), tb>>>(wo,0,0,DMODEL, woT,0,0,DMODEL, DMODEL,DMODEL, 1);
    transpose_rnd<<<dim3(FFDIM/32,  DMODEL/32, 1), tb>>>(w1,0,0,FFDIM,  w1T,0,0,DMODEL, DMODEL,FFDIM,  1);
    transpose_rnd<<<dim3(DMODEL/32, FFDIM/32,  1), tb>>>(w2,0,0,DMODEL, w2T,0,0,FFDIM,  FFDIM,DMODEL,  1);

    // 1. c = LN1(x)
    ln_kernel<<<ROWS, 256>>>(x, ln1, c);

    // 2. q/k/v = c @ w{q,k,v}   (outputs tf32-rounded)
    dim3 gA(DMODEL / 128, ROWS / 128, 1);
    gemm_kernel<128,128,64,32,0,true><<<gA,256,SM128>>>(c,0,0,DMODEL, wqT,0,0,DMODEL, q,0,0,DMODEL, nullptr,nullptr, ROWS,DMODEL,DMODEL, 1);
    gemm_kernel<128,128,64,32,0,true><<<gA,256,SM128>>>(c,0,0,DMODEL, wkT,0,0,DMODEL, k,0,0,DMODEL, nullptr,nullptr, ROWS,DMODEL,DMODEL, 1);
    gemm_kernel<128,128,64,32,0,true><<<gA,256,SM128>>>(c,0,0,DMODEL, wvT,0,0,DMODEL, v,0,0,DMODEL, nullptr,nullptr, ROWS,DMODEL,DMODEL, 1);

    // 2b. vT[b,h][d][j] = v[b][j][h*64+d]
    transpose_rnd<<<dim3(HDIM/32, SEQ/32, BATCH*NHEAD), tb>>>(
        v, rowStride, (long long)HDIM, DMODEL,
        vT, vTb, vTh, SEQ, SEQ, HDIM, NHEAD);

    // 3. s[b,h,i,j] = q_bh @ k_bh^T  (B = k rows [j][d], K contiguous)
    dim3 gS(SEQ / 128, SEQ / 128, BATCH * NHEAD);
    gemm_kernel<128,128,64,32,0,false><<<gS,256,SM128>>>(q,rowStride,HDIM,DMODEL, k,rowStride,HDIM,DMODEL, s,sOuter,sInner,SEQ, nullptr,nullptr, SEQ,SEQ,HDIM, NHEAD);

    // 4. softmax over j (rounded output)
    softmax_kernel<<<BATCH * NHEAD * SEQ, 256>>>(s);

    // 5. at_bh = p_bh @ v_bh   (B = vT rows [d][j])
    dim3 gPV(1, SEQ / 128, BATCH * NHEAD);
    gemm_kernel<128,64,32,32,0,true><<<gPV,256,SM64>>>(s,sOuter,sInner,SEQ, vT,vTb,vTh,SEQ, at,rowStride,HDIM,DMODEL, nullptr,nullptr, SEQ,HDIM,SEQ, NHEAD);

    // 6. x1 = x + 2*(at @ wo)
    gemm_kernel<128,128,64,32,3,false><<<gA,256,SM128>>>(at,0,0,DMODEL, woT,0,0,DMODEL, x1,0,0,DMODEL, nullptr, x, ROWS,DMODEL,DMODEL, 1);

    // 7-9. MLP #1
    ln_kernel<<<ROWS, 256>>>(x1, ln2, c);
    dim3 gF(FFDIM / 128, ROWS / 128, 1);
    gemm_kernel<128,128,64,32,1,true ><<<gF,256,SM128>>>(c,0,0,DMODEL, w1T,0,0,DMODEL, h,0,0,FFDIM, b1, nullptr, ROWS,FFDIM,DMODEL, 1);
    gemm_kernel<128,128,64,32,2,false><<<gA,256,SM128>>>(h,0,0,FFDIM, w2T,0,0,FFDIM, x2,0,0,DMODEL, b2, x1, ROWS,DMODEL,FFDIM, 1);

    // 10-12. MLP #2
    ln_kernel<<<ROWS, 256>>>(x2, ln2, c);
    gemm_kernel<128,128,64,32,1,true ><<<gF,256,SM128>>>(c,0,0,DMODEL, w1T,0,0,DMODEL, h,0,0,FFDIM, b1, nullptr, ROWS,FFDIM,DMODEL, 1);
    gemm_kernel<128,128,64,32,2,false><<<gA,256,SM128>>>(h,0,0,FFDIM, w2T,0,0,FFDIM, out,0,0,DMODEL, b2, x2, ROWS,DMODEL,FFDIM, 1);
}

// round 5
// speedup vs baseline: 2.4551x; 1.5942x over previous
#include <cuda_runtime.h>
#include <cuda_fp16.h>
#include <math.h>
#include <stdint.h>

// ---------------------------------------------------------------------------
// Transformer block: B=16, S=512, D=1024, H=16, HD=64, FF=4096
// FP16 tensor-core GEMMs (mma.sync.m16n8k16, fp32 accumulate),
// 3-stage cp.async pipeline, half operands everywhere, fp32 residual spine.
// ---------------------------------------------------------------------------

#define BATCH   16
#define SEQ     512
#define DMODEL  1024
#define NHEAD   16
#define HDIM    64
#define FFDIM   4096
#define ROWS    (BATCH * SEQ)          // 8192

// fp32 spine + scores
__device__ float  g_s  [(size_t)BATCH * NHEAD * SEQ * SEQ];  // scores fp32, 256 MB
__device__ float  g_x1 [ROWS * DMODEL];
__device__ float  g_x2 [ROWS * DMODEL];
// half operands
__device__ __half g_c  [ROWS * DMODEL];
__device__ __half g_q  [ROWS * DMODEL];
__device__ __half g_k  [ROWS * DMODEL];
__device__ __half g_v  [ROWS * DMODEL];
__device__ __half g_vT [ROWS * DMODEL];                      // [b,h][d][j]
__device__ __half g_p  [(size_t)BATCH * NHEAD * SEQ * SEQ];  // probs half, 128 MB
__device__ __half g_at [ROWS * DMODEL];
__device__ __half g_h  [ROWS * FFDIM];                       // 64 MB
// transposed half weights
__device__ __half g_wqT[DMODEL * DMODEL];
__device__ __half g_wkT[DMODEL * DMODEL];
__device__ __half g_wvT[DMODEL * DMODEL];
__device__ __half g_woT[DMODEL * DMODEL];
__device__ __half g_w1T[(size_t)DMODEL * FFDIM];
__device__ __half g_w2T[(size_t)DMODEL * FFDIM];

// ---------------------------------------------------------------------------
__device__ __forceinline__ float gelu_tanh(float x) {
    float x3 = x * x * x;
    float u  = 0.7978845608028654f * (x + 0.044715f * x3);
    return 0.5f * x * (1.0f + tanhf(u));
}

__device__ __forceinline__ void mma_f16(float* c, const uint32_t* a, const uint32_t* b) {
    asm volatile(
        "mma.sync.aligned.m16n8k16.row.col.f32.f16.f16.f32 "
        "{%0,%1,%2,%3}, {%4,%5,%6,%7}, {%8,%9}, {%0,%1,%2,%3};\n"
        : "+f"(c[0]), "+f"(c[1]), "+f"(c[2]), "+f"(c[3])
        : "r"(a[0]), "r"(a[1]), "r"(a[2]), "r"(a[3]),
          "r"(b[0]), "r"(b[1]));
}

__device__ __forceinline__ void cp16(uint32_t dst, const void* src) {
    asm volatile("cp.async.cg.shared.global [%0], [%1], 16;\n" :: "r"(dst), "l"(src));
}
__device__ __forceinline__ void cp_commit() {
    asm volatile("cp.async.commit_group;\n");
}
template<int N>
__device__ __forceinline__ void cp_wait() {
    asm volatile("cp.async.wait_group %0;\n" :: "n"(N));
}

// ---------------------------------------------------------------------------
// Batched transpose -> half:  out[z][c][r] = half(in[z][r][c])
// ---------------------------------------------------------------------------
template<typename TIN>
__global__ void transpose_h(const TIN* __restrict__ in, long long iOuter, long long iInner, int ldin,
                            __half* __restrict__ out, long long oOuter, long long oInner, int ldout,
                            int ic) {
    __shared__ float t[32][33];
    int z = blockIdx.z;
    const TIN* ib = in  + (z / ic) * iOuter + (z % ic) * iInner;
    __half*    ob = out + (z / ic) * oOuter + (z % ic) * oInner;
    int r0 = blockIdx.y * 32, c0 = blockIdx.x * 32;
    #pragma unroll
    for (int j = 0; j < 32; j += 8)
        t[threadIdx.y + j][threadIdx.x] = (float)ib[(size_t)(r0 + threadIdx.y + j) * ldin + c0 + threadIdx.x];
    __syncthreads();
    #pragma unroll
    for (int j = 0; j < 32; j += 8)
        ob[(size_t)(c0 + threadIdx.y + j) * ldout + r0 + threadIdx.x] =
            __float2half_rn(t[threadIdx.x][threadIdx.y + j]);
}

// ---------------------------------------------------------------------------
// LayerNorm: one block per row of 1024, half output
// ---------------------------------------------------------------------------
__global__ void ln_kernel(const float* __restrict__ x,
                          const float* __restrict__ scale,
                          __half* __restrict__ out) {
    int row = blockIdx.x, tid = threadIdx.x;
    const float4* xr = (const float4*)(x + (size_t)row * DMODEL);
    float4 v = xr[tid];
    float s = v.x + v.y + v.z + v.w;
    float q = v.x * v.x + v.y * v.y + v.z * v.z + v.w * v.w;
    #pragma unroll
    for (int o = 16; o > 0; o >>= 1) {
        s += __shfl_xor_sync(0xffffffffu, s, o);
        q += __shfl_xor_sync(0xffffffffu, q, o);
    }
    __shared__ float ss[8], qq[8];
    if ((tid & 31) == 0) { ss[tid >> 5] = s; qq[tid >> 5] = q; }
    __syncthreads();
    if (tid == 0) {
        float ts = 0.f, tq = 0.f;
        #pragma unroll
        for (int i = 0; i < 8; i++) { ts += ss[i]; tq += qq[i]; }
        ss[0] = ts; qq[0] = tq;
    }
    __syncthreads();
    float mean = ss[0] * (1.0f / DMODEL);
    float var  = qq[0] * (1.0f / DMODEL) - mean * mean;
    float r    = rsqrtf(var + 1e-6f);
    float4 sc  = ((const float4*)scale)[tid];
    __half2 o0 = __floats2half2_rn((v.x - mean) * r * sc.x, (v.y - mean) * r * sc.y);
    __half2 o1 = __floats2half2_rn((v.z - mean) * r * sc.z, (v.w - mean) * r * sc.w);
    __half2* op = (__half2*)(out + (size_t)row * DMODEL + tid * 4);
    op[0] = o0; op[1] = o1;
}

// ---------------------------------------------------------------------------
// Softmax rows of 512: fp32 scores in, half probs out, 0.125 pre-scale
// ---------------------------------------------------------------------------
__global__ void softmax_kernel(const float* __restrict__ s, __half* __restrict__ p) {
    size_t row = blockIdx.x;
    const float2* sp = (const float2*)(s + row * SEQ);
    int tid = threadIdx.x;
    float2 v = sp[tid];
    v.x *= 0.125f; v.y *= 0.125f;
    float m = fmaxf(v.x, v.y);
    #pragma unroll
    for (int o = 16; o > 0; o >>= 1) m = fmaxf(m, __shfl_xor_sync(0xffffffffu, m, o));
    __shared__ float rm[8], rs[8];
    if ((tid & 31) == 0) rm[tid >> 5] = m;
    __syncthreads();
    if (tid == 0) {
        float t = rm[0];
        #pragma unroll
        for (int i = 1; i < 8; i++) t = fmaxf(t, rm[i]);
        rm[0] = t;
    }
    __syncthreads();
    m = rm[0];
    float e0 = __expf(v.x - m), e1 = __expf(v.y - m);
    float sum = e0 + e1;
    #pragma unroll
    for (int o = 16; o > 0; o >>= 1) sum += __shfl_xor_sync(0xffffffffu, sum, o);
    if ((tid & 31) == 0) rs[tid >> 5] = sum;
    __syncthreads();
    if (tid == 0) {
        float t = 0.f;
        #pragma unroll
        for (int i = 0; i < 8; i++) t += rs[i];
        rs[0] = t;
    }
    __syncthreads();
    float inv = 1.0f / rs[0];
    ((__half2*)(p + row * SEQ))[tid] = __floats2half2_rn(e0 * inv, e1 * inv);
}

// ---------------------------------------------------------------------------
// Batched FP16 GEMM, fp32 accumulate, 3-stage cp.async pipeline.
// C[M,N] = A[M,K] * B^T where A is [M,K], B is [N,K], both half, K-contiguous.
// EPI: 0 none | 1 gelu(acc+bias) | 2 acc+bias+res | 3 res+2*acc
// OUT: float or __half
// ---------------------------------------------------------------------------
template<int BM, int BN, int WM, int WN, int EPI, typename OUT>
__global__ void __launch_bounds__(256, 2)
gemm_kernel(const __half* __restrict__ A, long long aOuter, long long aInner, int lda,
            const __half* __restrict__ B, long long bOuter, long long bInner, int ldb,
            OUT* __restrict__ C, long long cOuter, long long cInner, int ldc,
            const float* __restrict__ bias,
            const float* __restrict__ res,
            int M, int N, int K, int innerCount) {
    constexpr int BK = 32;                 // halves per K-tile
    constexpr int NSTAGES = 3;
    constexpr int WARPS_M = BM / WM;
    constexpr int WARPS_N = BN / WN;
    static_assert(WARPS_M * WARPS_N == 8, "8 warps");
    constexpr int MT = WM / 16;
    constexpr int NT = WN / 8;
    constexpr int STRIDE = BK + 8;         // 40 halves = 80B rows, conflict-free
    constexpr int A_H = BM * STRIDE;
    constexpr int B_H = BN * STRIDE;
    constexpr int STAGE_H = A_H + B_H;

    extern __shared__ __half smem[];
    uint32_t smem_u32 = (uint32_t)__cvta_generic_to_shared(smem);

    int z  = blockIdx.z;
    int zo = z / innerCount, zi = z % innerCount;
    const __half* Ab = A + zo * aOuter + zi * aInner;
    const __half* Bb = B + zo * bOuter + zi * bInner;
    OUT*          Cb = C + zo * cOuter + zi * cInner;
    const float*  Rb = (EPI == 2 || EPI == 3) ? (res + zo * cOuter + zi * cInner) : nullptr;

    int m0 = blockIdx.y * BM;
    int n0 = blockIdx.x * BN;

    int tid  = threadIdx.x;
    int warp = tid >> 5, lane = tid & 31;
    int wm = (warp % WARPS_M) * WM;
    int wn = (warp / WARPS_M) * WN;
    int g  = lane >> 2, tc = lane & 3;

    // loader: 16B chunks = 8 halves; row = tid>>2 (stride 64), k8 = tid&3
    int l_r  = tid >> 2;
    int l_k8 = tid & 3;
    const __half* Aptr = Ab + (size_t)(m0 + l_r) * lda + l_k8 * 8;
    const __half* Bptr = Bb + (size_t)(n0 + l_r) * ldb + l_k8 * 8;

    float acc[MT][NT][4];
    #pragma unroll
    for (int i = 0; i < MT; i++)
        #pragma unroll
        for (int j = 0; j < NT; j++)
            #pragma unroll
            for (int e = 0; e < 4; e++) acc[i][j][e] = 0.f;

    const int ntiles = K / BK;

    auto load_tile = [&](int t, int s) {
        int kt = t * BK;
        uint32_t aBase = smem_u32 + (uint32_t)(s * STAGE_H) * 2u;
        uint32_t bBase = aBase + (uint32_t)A_H * 2u;
        #pragma unroll
        for (int i = 0; i < BM / 64; ++i)
            cp16(aBase + (uint32_t)((l_r + i * 64) * STRIDE + l_k8 * 8) * 2u,
                 Aptr + (size_t)(i * 64) * lda + kt);
        #pragma unroll
        for (int i = 0; i < BN / 64; ++i)
            cp16(bBase + (uint32_t)((l_r + i * 64) * STRIDE + l_k8 * 8) * 2u,
                 Bptr + (size_t)(i * 64) * ldb + kt);
    };

    #pragma unroll
    for (int s = 0; s < NSTAGES - 1; ++s) {
        if (s < ntiles) load_tile(s, s);
        cp_commit();
    }

    for (int t = 0; t < ntiles; ++t) {
        cp_wait<NSTAGES - 2>();
        __syncthreads();

        int tn = t + NSTAGES - 1;
        if (tn < ntiles) load_tile(tn, tn % NSTAGES);
        cp_commit();

        int cur = t % NSTAGES;
        const __half* Asc = smem + cur * STAGE_H;
        const __half* Bsc = Asc + A_H;

        #pragma unroll
        for (int ks = 0; ks < BK / 16; ++ks) {          // 2 K-steps of 16
            uint32_t af[MT][4], bf[NT][2];
            #pragma unroll
            for (int mt = 0; mt < MT; ++mt) {
                int r = wm + mt * 16;
                const __half* p0 = Asc + (r + g    ) * STRIDE + ks * 16 + tc * 2;
                const __half* p1 = Asc + (r + g + 8) * STRIDE + ks * 16 + tc * 2;
                af[mt][0] = *(const uint32_t*)(p0);
                af[mt][1] = *(const uint32_t*)(p1);
                af[mt][2] = *(const uint32_t*)(p0 + 8);
                af[mt][3] = *(const uint32_t*)(p1 + 8);
            }
            #pragma unroll
            for (int nt = 0; nt < NT; ++nt) {
                const __half* pb = Bsc + (wn + nt * 8 + g) * STRIDE + ks * 16 + tc * 2;
                bf[nt][0] = *(const uint32_t*)(pb);
                bf[nt][1] = *(const uint32_t*)(pb + 8);
            }
            #pragma unroll
            for (int mt = 0; mt < MT; ++mt)
                #pragma unroll
                for (int nt = 0; nt < NT; ++nt)
                    mma_f16(acc[mt][nt], af[mt], bf[nt]);
        }
    }

    // ---- epilogue ----
    #pragma unroll
    for (int mt = 0; mt < MT; ++mt) {
        #pragma unroll
        for (int nt = 0; nt < NT; ++nt) {
            int col = n0 + wn + nt * 8 + tc * 2;
            #pragma unroll
            for (int hrow = 0; hrow < 2; ++hrow) {
                int row  = m0 + wm + mt * 16 + g + hrow * 8;
                float v0 = acc[mt][nt][hrow * 2 + 0];
                float v1 = acc[mt][nt][hrow * 2 + 1];
                size_t off = (size_t)row * ldc + col;
                if (EPI == 1) {
                    v0 = gelu_tanh(v0 + bias[col]);
                    v1 = gelu_tanh(v1 + bias[col + 1]);
                } else if (EPI == 2) {
                    v0 = v0 + bias[col]     + Rb[off];
                    v1 = v1 + bias[col + 1] + Rb[off + 1];
                } else if (EPI == 3) {
                    v0 = 2.0f * v0 + Rb[off];
                    v1 = 2.0f * v1 + Rb[off + 1];
                }
                if (sizeof(OUT) == 2) {
                    *(__half2*)((__half*)Cb + off) = __floats2half2_rn(v0, v1);
                } else {
                    *(float2*)((float*)Cb + off) = make_float2(v0, v1);
                }
            }
        }
    }
}

// ---------------------------------------------------------------------------
// host launch
// ---------------------------------------------------------------------------
extern "C" void kernel_launch(void* const* d_in, const int* in_sizes, int n_in,
                              void* d_out, int out_size) {
    const float* x   = (const float*)d_in[0];
    const float* wq  = (const float*)d_in[1];
    const float* wk  = (const float*)d_in[2];
    const float* wv  = (const float*)d_in[3];
    const float* wo  = (const float*)d_in[4];
    const float* ln1 = (const float*)d_in[5];
    const float* ln2 = (const float*)d_in[6];
    const float* w1  = (const float*)d_in[7];
    const float* b1  = (const float*)d_in[8];
    const float* w2  = (const float*)d_in[9];
    const float* b2  = (const float*)d_in[10];
    float* out = (float*)d_out;

    float *s, *x1, *x2;
    __half *c, *q, *k, *v, *vT, *p, *at, *h;
    __half *wqT, *wkT, *wvT, *woT, *w1T, *w2T;
    cudaGetSymbolAddress((void**)&s,  g_s);
    cudaGetSymbolAddress((void**)&x1, g_x1);
    cudaGetSymbolAddress((void**)&x2, g_x2);
    cudaGetSymbolAddress((void**)&c,  g_c);
    cudaGetSymbolAddress((void**)&q,  g_q);
    cudaGetSymbolAddress((void**)&k,  g_k);
    cudaGetSymbolAddress((void**)&v,  g_v);
    cudaGetSymbolAddress((void**)&vT, g_vT);
    cudaGetSymbolAddress((void**)&p,  g_p);
    cudaGetSymbolAddress((void**)&at, g_at);
    cudaGetSymbolAddress((void**)&h,  g_h);
    cudaGetSymbolAddress((void**)&wqT, g_wqT);
    cudaGetSymbolAddress((void**)&wkT, g_wkT);
    cudaGetSymbolAddress((void**)&wvT, g_wvT);
    cudaGetSymbolAddress((void**)&woT, g_woT);
    cudaGetSymbolAddress((void**)&w1T, g_w1T);
    cudaGetSymbolAddress((void**)&w2T, g_w2T);

    // smem: (BM + BN) * 40 halves * 3 stages * 2 bytes
    const int SM128 = (128 + 128) * 40 * 3 * 2;   // 61440
    const int SM64  = (128 +  64) * 40 * 3 * 2;   // 46080

    static bool attr_done = false;
    if (!attr_done) {
        cudaFuncSetAttribute(gemm_kernel<128,128,64,32,0,__half>, cudaFuncAttributeMaxDynamicSharedMemorySize, SM128);
        cudaFuncSetAttribute(gemm_kernel<128,128,64,32,0,float >, cudaFuncAttributeMaxDynamicSharedMemorySize, SM128);
        cudaFuncSetAttribute(gemm_kernel<128, 64,32,32,0,__half>, cudaFuncAttributeMaxDynamicSharedMemorySize, SM64);
        cudaFuncSetAttribute(gemm_kernel<128,128,64,32,1,__half>, cudaFuncAttributeMaxDynamicSharedMemorySize, SM128);
        cudaFuncSetAttribute(gemm_kernel<128,128,64,32,2,float >, cudaFuncAttributeMaxDynamicSharedMemorySize, SM128);
        cudaFuncSetAttribute(gemm_kernel<128,128,64,32,3,float >, cudaFuncAttributeMaxDynamicSharedMemorySize, SM128);
        attr_done = true;
    }

    const long long rowStride = (long long)SEQ * DMODEL;
    const long long sInner = (long long)SEQ * SEQ;
    const long long sOuter = (long long)NHEAD * SEQ * SEQ;
    const long long vTb = (long long)NHEAD * HDIM * SEQ;
    const long long vTh = (long long)HDIM * SEQ;

    dim3 tb(32, 8);

    // 0. weight prep: transpose + half convert
    transpose_h<float><<<dim3(DMODEL/32, DMODEL/32, 1), tb>>>(wq,0,0,DMODEL, wqT,0,0,DMODEL, 1);
    transpose_h<float><<<dim3(DMODEL/32, DMODEL/32, 1), tb>>>(wk,0,0,DMODEL, wkT,0,0,DMODEL, 1);
    transpose_h<float><<<dim3(DMODEL/32, DMODEL/32, 1), tb>>>(wv,0,0,DMODEL, wvT,0,0,DMODEL, 1);
    transpose_h<float><<<dim3(DMODEL/32, DMODEL/32, 1), tb>>>(wo,0,0,DMODEL, woT,0,0,DMODEL, 1);
    transpose_h<float><<<dim3(FFDIM/32,  DMODEL/32, 1), tb>>>(w1,0,0,FFDIM,  w1T,0,0,DMODEL, 1);
    transpose_h<float><<<dim3(DMODEL/32, FFDIM/32,  1), tb>>>(w2,0,0,DMODEL, w2T,0,0,FFDIM,  1);

    // 1. c = LN1(x)
    ln_kernel<<<ROWS, 256>>>(x, ln1, c);

    // 2. q/k/v = c @ w{q,k,v}
    dim3 gA(DMODEL / 128, ROWS / 128, 1);
    gemm_kernel<128,128,64,32,0,__half><<<gA,256,SM128>>>(c,0,0,DMODEL, wqT,0,0,DMODEL, q,0,0,DMODEL, nullptr,nullptr, ROWS,DMODEL,DMODEL, 1);
    gemm_kernel<128,128,64,32,0,__half><<<gA,256,SM128>>>(c,0,0,DMODEL, wkT,0,0,DMODEL, k,0,0,DMODEL, nullptr,nullptr, ROWS,DMODEL,DMODEL, 1);
    gemm_kernel<128,128,64,32,0,__half><<<gA,256,SM128>>>(c,0,0,DMODEL, wvT,0,0,DMODEL, v,0,0,DMODEL, nullptr,nullptr, ROWS,DMODEL,DMODEL, 1);

    // 2b. vT[b,h][d][j] = v[b][j][h*64+d]
    transpose_h<__half><<<dim3(HDIM/32, SEQ/32, BATCH*NHEAD), tb>>>(
        v, rowStride, (long long)HDIM, DMODEL, vT, vTb, vTh, SEQ, NHEAD);

    // 3. s[b,h,i,j] = q_bh @ k_bh^T  (fp32 scores out)
    dim3 gS(SEQ / 128, SEQ / 128, BATCH * NHEAD);
    gemm_kernel<128,128,64,32,0,float><<<gS,256,SM128>>>(q,rowStride,HDIM,DMODEL, k,rowStride,HDIM,DMODEL, s,sOuter,sInner,SEQ, nullptr,nullptr, SEQ,SEQ,HDIM, NHEAD);

    // 4. softmax -> half probs
    softmax_kernel<<<BATCH * NHEAD * SEQ, 256>>>(s, p);

    // 5. at_bh = p_bh @ v_bh
    dim3 gPV(1, SEQ / 128, BATCH * NHEAD);
    gemm_kernel<128,64,32,32,0,__half><<<gPV,256,SM64>>>(p,sOuter,sInner,SEQ, vT,vTb,vTh,SEQ, at,rowStride,HDIM,DMODEL, nullptr,nullptr, SEQ,HDIM,SEQ, NHEAD);

    // 6. x1 = x + 2*(at @ wo)
    gemm_kernel<128,128,64,32,3,float><<<gA,256,SM128>>>(at,0,0,DMODEL, woT,0,0,DMODEL, x1,0,0,DMODEL, nullptr, x, ROWS,DMODEL,DMODEL, 1);

    // 7-9. MLP #1
    ln_kernel<<<ROWS, 256>>>(x1, ln2, c);
    dim3 gF(FFDIM / 128, ROWS / 128, 1);
    gemm_kernel<128,128,64,32,1,__half><<<gF,256,SM128>>>(c,0,0,DMODEL, w1T,0,0,DMODEL, h,0,0,FFDIM, b1, nullptr, ROWS,FFDIM,DMODEL, 1);
    gemm_kernel<128,128,64,32,2,float ><<<gA,256,SM128>>>(h,0,0,FFDIM, w2T,0,0,FFDIM, x2,0,0,DMODEL, b2, x1, ROWS,DMODEL,FFDIM, 1);

    // 10-12. MLP #2
    ln_kernel<<<ROWS, 256>>>(x2, ln2, c);
    gemm_kernel<128,128,64,32,1,__half><<<gF,256,SM128>>>(c,0,0,DMODEL, w1T,0,0,DMODEL, h,0,0,FFDIM, b1, nullptr, ROWS,FFDIM,DMODEL, 1);
    gemm_kernel<128,128,64,32,2,float ><<<gA,256,SM128>>>(h,0,0,FFDIM, w2T,0,0,FFDIM, out,0,0,DMODEL, b2, x2, ROWS,DMODEL,FFDIM, 1);
}

// round 6
// speedup vs baseline: 2.7380x; 1.1152x over previous
#include <cuda_runtime.h>
#include <cuda_fp16.h>
#include <math.h>
#include <stdint.h>

// ---------------------------------------------------------------------------
// Transformer block: B=16, S=512, D=1024, H=16, HD=64, FF=4096
// FP16 tensor-core GEMMs (mma.sync.m16n8k16, fp32 accumulate),
// 3-stage cp.async pipeline, fused flash-attention (QK^T+softmax+PV).
// ---------------------------------------------------------------------------

#define BATCH   16
#define SEQ     512
#define DMODEL  1024
#define NHEAD   16
#define HDIM    64
#define FFDIM   4096
#define ROWS    (BATCH * SEQ)          // 8192

// fp32 spine
__device__ float  g_x1 [ROWS * DMODEL];
__device__ float  g_x2 [ROWS * DMODEL];
// half operands
__device__ __half g_c  [ROWS * DMODEL];
__device__ __half g_q  [ROWS * DMODEL];
__device__ __half g_k  [ROWS * DMODEL];
__device__ __half g_v  [ROWS * DMODEL];
__device__ __half g_vT [ROWS * DMODEL];                      // [b,h][d][j]
__device__ __half g_at [ROWS * DMODEL];
__device__ __half g_h  [ROWS * FFDIM];                       // 64 MB
// transposed half weights
__device__ __half g_wqT[DMODEL * DMODEL];
__device__ __half g_wkT[DMODEL * DMODEL];
__device__ __half g_wvT[DMODEL * DMODEL];
__device__ __half g_woT[DMODEL * DMODEL];
__device__ __half g_w1T[(size_t)DMODEL * FFDIM];
__device__ __half g_w2T[(size_t)DMODEL * FFDIM];

// ---------------------------------------------------------------------------
__device__ __forceinline__ float gelu_tanh(float x) {
    float x3 = x * x * x;
    float u  = 0.7978845608028654f * (x + 0.044715f * x3);
    return 0.5f * x * (1.0f + tanhf(u));
}

__device__ __forceinline__ void mma_f16(float* c, const uint32_t* a, const uint32_t* b) {
    asm volatile(
        "mma.sync.aligned.m16n8k16.row.col.f32.f16.f16.f32 "
        "{%0,%1,%2,%3}, {%4,%5,%6,%7}, {%8,%9}, {%0,%1,%2,%3};\n"
        : "+f"(c[0]), "+f"(c[1]), "+f"(c[2]), "+f"(c[3])
        : "r"(a[0]), "r"(a[1]), "r"(a[2]), "r"(a[3]),
          "r"(b[0]), "r"(b[1]));
}

__device__ __forceinline__ void cp16(uint32_t dst, const void* src) {
    asm volatile("cp.async.cg.shared.global [%0], [%1], 16;\n" :: "r"(dst), "l"(src));
}
__device__ __forceinline__ void cp_commit() {
    asm volatile("cp.async.commit_group;\n");
}
template<int N>
__device__ __forceinline__ void cp_wait() {
    asm volatile("cp.async.wait_group %0;\n" :: "n"(N));
}

__device__ __forceinline__ uint32_t packh2(float a, float b) {
    __half2 h = __floats2half2_rn(a, b);
    return *(uint32_t*)&h;
}

// ---------------------------------------------------------------------------
// Batched transpose -> half:  out[z][c][r] = half(in[z][r][c])
// ---------------------------------------------------------------------------
template<typename TIN>
__global__ void transpose_h(const TIN* __restrict__ in, long long iOuter, long long iInner, int ldin,
                            __half* __restrict__ out, long long oOuter, long long oInner, int ldout,
                            int ic) {
    __shared__ float t[32][33];
    int z = blockIdx.z;
    const TIN* ib = in  + (z / ic) * iOuter + (z % ic) * iInner;
    __half*    ob = out + (z / ic) * oOuter + (z % ic) * oInner;
    int r0 = blockIdx.y * 32, c0 = blockIdx.x * 32;
    #pragma unroll
    for (int j = 0; j < 32; j += 8)
        t[threadIdx.y + j][threadIdx.x] = (float)ib[(size_t)(r0 + threadIdx.y + j) * ldin + c0 + threadIdx.x];
    __syncthreads();
    #pragma unroll
    for (int j = 0; j < 32; j += 8)
        ob[(size_t)(c0 + threadIdx.y + j) * ldout + r0 + threadIdx.x] =
            __float2half_rn(t[threadIdx.x][threadIdx.y + j]);
}

// ---------------------------------------------------------------------------
// LayerNorm: one block per row of 1024, half output
// ---------------------------------------------------------------------------
__global__ void ln_kernel(const float* __restrict__ x,
                          const float* __restrict__ scale,
                          __half* __restrict__ out) {
    int row = blockIdx.x, tid = threadIdx.x;
    const float4* xr = (const float4*)(x + (size_t)row * DMODEL);
    float4 v = xr[tid];
    float s = v.x + v.y + v.z + v.w;
    float q = v.x * v.x + v.y * v.y + v.z * v.z + v.w * v.w;
    #pragma unroll
    for (int o = 16; o > 0; o >>= 1) {
        s += __shfl_xor_sync(0xffffffffu, s, o);
        q += __shfl_xor_sync(0xffffffffu, q, o);
    }
    __shared__ float ss[8], qq[8];
    if ((tid & 31) == 0) { ss[tid >> 5] = s; qq[tid >> 5] = q; }
    __syncthreads();
    if (tid == 0) {
        float ts = 0.f, tq = 0.f;
        #pragma unroll
        for (int i = 0; i < 8; i++) { ts += ss[i]; tq += qq[i]; }
        ss[0] = ts; qq[0] = tq;
    }
    __syncthreads();
    float mean = ss[0] * (1.0f / DMODEL);
    float var  = qq[0] * (1.0f / DMODEL) - mean * mean;
    float r    = rsqrtf(var + 1e-6f);
    float4 sc  = ((const float4*)scale)[tid];
    __half2 o0 = __floats2half2_rn((v.x - mean) * r * sc.x, (v.y - mean) * r * sc.y);
    __half2 o1 = __floats2half2_rn((v.z - mean) * r * sc.z, (v.w - mean) * r * sc.w);
    __half2* op = (__half2*)(out + (size_t)row * DMODEL + tid * 4);
    op[0] = o0; op[1] = o1;
}

// ---------------------------------------------------------------------------
// Fused flash attention.  grid = (S/128, B*H), 256 threads.
// q is pre-scaled by 1/8.  Q tile 128x64, full K 512x64, full V^T 64x512
// in smem.  8 warps x 16 rows; online softmax; probs stay in registers.
// Output at[row][h*64+d] (half).
// ---------------------------------------------------------------------------
#define QS_STRIDE 72
#define KS_STRIDE 72
#define VS_STRIDE 520

__global__ void __launch_bounds__(256, 1)
flash_kernel(const __half* __restrict__ q, const __half* __restrict__ k,
             const __half* __restrict__ vT, __half* __restrict__ at) {
    extern __shared__ __half sm[];
    __half* Qs = sm;                               // 128 x 72
    __half* Ks = Qs + 128 * QS_STRIDE;             // 512 x 72
    __half* Vs = Ks + 512 * KS_STRIDE;             // 64 x 520

    int bh = blockIdx.y;
    int b  = bh >> 4;
    int h  = bh & 15;
    int i0 = blockIdx.x * 128;

    const __half* Qg = q  + ((size_t)(b * SEQ + i0)) * DMODEL + h * HDIM;
    const __half* Kg = k  + ((size_t)(b * SEQ))      * DMODEL + h * HDIM;
    const __half* Vg = vT + ((size_t)b * NHEAD + h) * HDIM * SEQ;

    int tid = threadIdx.x;
    uint32_t Qsb = (uint32_t)__cvta_generic_to_shared(Qs);
    uint32_t Ksb = (uint32_t)__cvta_generic_to_shared(Ks);
    uint32_t Vsb = (uint32_t)__cvta_generic_to_shared(Vs);

    #pragma unroll
    for (int i = 0; i < 4; i++) {                  // Q: 128 rows x 8 chunks
        int idx = tid + i * 256;
        int r = idx >> 3, c = idx & 7;
        cp16(Qsb + (uint32_t)(r * QS_STRIDE + c * 8) * 2u, Qg + (size_t)r * DMODEL + c * 8);
    }
    #pragma unroll
    for (int i = 0; i < 16; i++) {                 // K: 512 rows x 8 chunks
        int idx = tid + i * 256;
        int r = idx >> 3, c = idx & 7;
        cp16(Ksb + (uint32_t)(r * KS_STRIDE + c * 8) * 2u, Kg + (size_t)r * DMODEL + c * 8);
    }
    #pragma unroll
    for (int i = 0; i < 16; i++) {                 // V^T: 64 rows x 64 chunks
        int idx = tid + i * 256;
        int r = idx >> 6, c = idx & 63;
        cp16(Vsb + (uint32_t)(r * VS_STRIDE + c * 8) * 2u, Vg + (size_t)r * SEQ + c * 8);
    }
    cp_commit();
    cp_wait<0>();
    __syncthreads();

    int warp = tid >> 5, lane = tid & 31;
    int g = lane >> 2, tc = lane & 3;
    int wr = warp * 16;

    float m0 = -1e30f, m1 = -1e30f, l0 = 0.f, l1 = 0.f;
    float O[8][4];
    #pragma unroll
    for (int dt = 0; dt < 8; dt++)
        #pragma unroll
        for (int e = 0; e < 4; e++) O[dt][e] = 0.f;

    const __half* qrow0 = Qs + (wr + g) * QS_STRIDE + tc * 2;

    for (int jc = 0; jc < 4; jc++) {
        int j0 = jc * 128;
        float S[16][4];
        #pragma unroll
        for (int nt = 0; nt < 16; nt++)
            #pragma unroll
            for (int e = 0; e < 4; e++) S[nt][e] = 0.f;

        // S = Q @ K^T  (chunk: 128 q-rows x 128 j-cols, per warp 16 x 128)
        #pragma unroll
        for (int ks = 0; ks < 4; ks++) {
            uint32_t a[4];
            const __half* p0 = qrow0 + ks * 16;
            const __half* p1 = p0 + 8 * QS_STRIDE;
            a[0] = *(const uint32_t*)(p0);
            a[1] = *(const uint32_t*)(p1);
            a[2] = *(const uint32_t*)(p0 + 8);
            a[3] = *(const uint32_t*)(p1 + 8);
            #pragma unroll
            for (int nt = 0; nt < 16; nt++) {
                const __half* pb = Ks + (j0 + nt * 8 + g) * KS_STRIDE + ks * 16 + tc * 2;
                uint32_t bf[2] = { *(const uint32_t*)(pb), *(const uint32_t*)(pb + 8) };
                mma_f16(S[nt], a, bf);
            }
        }

        // online softmax (rows g and g+8 of this warp's 16)
        float mx0 = -1e30f, mx1 = -1e30f;
        #pragma unroll
        for (int nt = 0; nt < 16; nt++) {
            mx0 = fmaxf(mx0, fmaxf(S[nt][0], S[nt][1]));
            mx1 = fmaxf(mx1, fmaxf(S[nt][2], S[nt][3]));
        }
        mx0 = fmaxf(mx0, __shfl_xor_sync(0xffffffffu, mx0, 1));
        mx0 = fmaxf(mx0, __shfl_xor_sync(0xffffffffu, mx0, 2));
        mx1 = fmaxf(mx1, __shfl_xor_sync(0xffffffffu, mx1, 1));
        mx1 = fmaxf(mx1, __shfl_xor_sync(0xffffffffu, mx1, 2));
        float mn0 = fmaxf(m0, mx0), mn1 = fmaxf(m1, mx1);
        float al0 = __expf(m0 - mn0), al1 = __expf(m1 - mn1);
        m0 = mn0; m1 = mn1;

        float rs0 = 0.f, rs1 = 0.f;
        #pragma unroll
        for (int nt = 0; nt < 16; nt++) {
            S[nt][0] = __expf(S[nt][0] - mn0);
            S[nt][1] = __expf(S[nt][1] - mn0);
            S[nt][2] = __expf(S[nt][2] - mn1);
            S[nt][3] = __expf(S[nt][3] - mn1);
            rs0 += S[nt][0] + S[nt][1];
            rs1 += S[nt][2] + S[nt][3];
        }
        rs0 += __shfl_xor_sync(0xffffffffu, rs0, 1);
        rs0 += __shfl_xor_sync(0xffffffffu, rs0, 2);
        rs1 += __shfl_xor_sync(0xffffffffu, rs1, 1);
        rs1 += __shfl_xor_sync(0xffffffffu, rs1, 2);
        l0 = l0 * al0 + rs0;
        l1 = l1 * al1 + rs1;

        #pragma unroll
        for (int dt = 0; dt < 8; dt++) {
            O[dt][0] *= al0; O[dt][1] *= al0;
            O[dt][2] *= al1; O[dt][3] *= al1;
        }

        // O += P @ V  (P fragments built directly from S accumulators)
        #pragma unroll
        for (int kp = 0; kp < 8; kp++) {
            uint32_t a[4];
            a[0] = packh2(S[2*kp  ][0], S[2*kp  ][1]);
            a[1] = packh2(S[2*kp  ][2], S[2*kp  ][3]);
            a[2] = packh2(S[2*kp+1][0], S[2*kp+1][1]);
            a[3] = packh2(S[2*kp+1][2], S[2*kp+1][3]);
            #pragma unroll
            for (int dt = 0; dt < 8; dt++) {
                const __half* pb = Vs + (dt * 8 + g) * VS_STRIDE + j0 + kp * 16 + tc * 2;
                uint32_t bf[2] = { *(const uint32_t*)(pb), *(const uint32_t*)(pb + 8) };
                mma_f16(O[dt], a, bf);
            }
        }
    }

    float inv0 = 1.0f / l0, inv1 = 1.0f / l1;
    int row0 = b * SEQ + i0 + wr + g;
    __half* ob = at + (size_t)row0 * DMODEL + h * HDIM;
    #pragma unroll
    for (int dt = 0; dt < 8; dt++) {
        __half2 o0 = __floats2half2_rn(O[dt][0] * inv0, O[dt][1] * inv0);
        __half2 o1 = __floats2half2_rn(O[dt][2] * inv1, O[dt][3] * inv1);
        *(__half2*)(ob + dt * 8 + tc * 2)                        = o0;
        *(__half2*)(ob + (size_t)8 * DMODEL + dt * 8 + tc * 2)   = o1;
    }
}

// ---------------------------------------------------------------------------
// Batched FP16 GEMM, fp32 accumulate, 3-stage cp.async pipeline.
// C[M,N] = A[M,K] * B^T where A is [M,K], B is [N,K], both half, K-contiguous.
// EPI: 0 none | 1 gelu(acc+bias) | 2 acc+bias+res | 3 res+2*acc | 4 acc*0.125
// ---------------------------------------------------------------------------
template<int BM, int BN, int WM, int WN, int EPI, typename OUT>
__global__ void __launch_bounds__(256, 2)
gemm_kernel(const __half* __restrict__ A, long long aOuter, long long aInner, int lda,
            const __half* __restrict__ B, long long bOuter, long long bInner, int ldb,
            OUT* __restrict__ C, long long cOuter, long long cInner, int ldc,
            const float* __restrict__ bias,
            const float* __restrict__ res,
            int M, int N, int K, int innerCount) {
    constexpr int BK = 32;
    constexpr int NSTAGES = 3;
    constexpr int WARPS_M = BM / WM;
    constexpr int WARPS_N = BN / WN;
    static_assert(WARPS_M * WARPS_N == 8, "8 warps");
    constexpr int MT = WM / 16;
    constexpr int NT = WN / 8;
    constexpr int STRIDE = BK + 8;
    constexpr int A_H = BM * STRIDE;
    constexpr int B_H = BN * STRIDE;
    constexpr int STAGE_H = A_H + B_H;

    extern __shared__ __half smem[];
    uint32_t smem_u32 = (uint32_t)__cvta_generic_to_shared(smem);

    int z  = blockIdx.z;
    int zo = z / innerCount, zi = z % innerCount;
    const __half* Ab = A + zo * aOuter + zi * aInner;
    const __half* Bb = B + zo * bOuter + zi * bInner;
    OUT*          Cb = C + zo * cOuter + zi * cInner;
    const float*  Rb = (EPI == 2 || EPI == 3) ? (res + zo * cOuter + zi * cInner) : nullptr;

    int m0 = blockIdx.y * BM;
    int n0 = blockIdx.x * BN;

    int tid  = threadIdx.x;
    int warp = tid >> 5, lane = tid & 31;
    int wm = (warp % WARPS_M) * WM;
    int wn = (warp / WARPS_M) * WN;
    int g  = lane >> 2, tc = lane & 3;

    int l_r  = tid >> 2;
    int l_k8 = tid & 3;
    const __half* Aptr = Ab + (size_t)(m0 + l_r) * lda + l_k8 * 8;
    const __half* Bptr = Bb + (size_t)(n0 + l_r) * ldb + l_k8 * 8;

    float acc[MT][NT][4];
    #pragma unroll
    for (int i = 0; i < MT; i++)
        #pragma unroll
        for (int j = 0; j < NT; j++)
            #pragma unroll
            for (int e = 0; e < 4; e++) acc[i][j][e] = 0.f;

    const int ntiles = K / BK;

    auto load_tile = [&](int t, int s) {
        int kt = t * BK;
        uint32_t aBase = smem_u32 + (uint32_t)(s * STAGE_H) * 2u;
        uint32_t bBase = aBase + (uint32_t)A_H * 2u;
        #pragma unroll
        for (int i = 0; i < BM / 64; ++i)
            cp16(aBase + (uint32_t)((l_r + i * 64) * STRIDE + l_k8 * 8) * 2u,
                 Aptr + (size_t)(i * 64) * lda + kt);
        #pragma unroll
        for (int i = 0; i < BN / 64; ++i)
            cp16(bBase + (uint32_t)((l_r + i * 64) * STRIDE + l_k8 * 8) * 2u,
                 Bptr + (size_t)(i * 64) * ldb + kt);
    };

    #pragma unroll
    for (int s = 0; s < NSTAGES - 1; ++s) {
        if (s < ntiles) load_tile(s, s);
        cp_commit();
    }

    for (int t = 0; t < ntiles; ++t) {
        cp_wait<NSTAGES - 2>();
        __syncthreads();

        int tn = t + NSTAGES - 1;
        if (tn < ntiles) load_tile(tn, tn % NSTAGES);
        cp_commit();

        int cur = t % NSTAGES;
        const __half* Asc = smem + cur * STAGE_H;
        const __half* Bsc = Asc + A_H;

        #pragma unroll
        for (int ks = 0; ks < BK / 16; ++ks) {
            uint32_t af[MT][4], bf[NT][2];
            #pragma unroll
            for (int mt = 0; mt < MT; ++mt) {
                int r = wm + mt * 16;
                const __half* p0 = Asc + (r + g    ) * STRIDE + ks * 16 + tc * 2;
                const __half* p1 = Asc + (r + g + 8) * STRIDE + ks * 16 + tc * 2;
                af[mt][0] = *(const uint32_t*)(p0);
                af[mt][1] = *(const uint32_t*)(p1);
                af[mt][2] = *(const uint32_t*)(p0 + 8);
                af[mt][3] = *(const uint32_t*)(p1 + 8);
            }
            #pragma unroll
            for (int nt = 0; nt < NT; ++nt) {
                const __half* pb = Bsc + (wn + nt * 8 + g) * STRIDE + ks * 16 + tc * 2;
                bf[nt][0] = *(const uint32_t*)(pb);
                bf[nt][1] = *(const uint32_t*)(pb + 8);
            }
            #pragma unroll
            for (int mt = 0; mt < MT; ++mt)
                #pragma unroll
                for (int nt = 0; nt < NT; ++nt)
                    mma_f16(acc[mt][nt], af[mt], bf[nt]);
        }
    }

    // ---- epilogue ----
    #pragma unroll
    for (int mt = 0; mt < MT; ++mt) {
        #pragma unroll
        for (int nt = 0; nt < NT; ++nt) {
            int col = n0 + wn + nt * 8 + tc * 2;
            #pragma unroll
            for (int hrow = 0; hrow < 2; ++hrow) {
                int row  = m0 + wm + mt * 16 + g + hrow * 8;
                float v0 = acc[mt][nt][hrow * 2 + 0];
                float v1 = acc[mt][nt][hrow * 2 + 1];
                size_t off = (size_t)row * ldc + col;
                if (EPI == 1) {
                    v0 = gelu_tanh(v0 + bias[col]);
                    v1 = gelu_tanh(v1 + bias[col + 1]);
                } else if (EPI == 2) {
                    v0 = v0 + bias[col]     + Rb[off];
                    v1 = v1 + bias[col + 1] + Rb[off + 1];
                } else if (EPI == 3) {
                    v0 = 2.0f * v0 + Rb[off];
                    v1 = 2.0f * v1 + Rb[off + 1];
                } else if (EPI == 4) {
                    v0 *= 0.125f;
                    v1 *= 0.125f;
                }
                if (sizeof(OUT) == 2) {
                    *(__half2*)((__half*)Cb + off) = __floats2half2_rn(v0, v1);
                } else {
                    *(float2*)((float*)Cb + off) = make_float2(v0, v1);
                }
            }
        }
    }
}

// ---------------------------------------------------------------------------
// host launch
// ---------------------------------------------------------------------------
extern "C" void kernel_launch(void* const* d_in, const int* in_sizes, int n_in,
                              void* d_out, int out_size) {
    const float* x   = (const float*)d_in[0];
    const float* wq  = (const float*)d_in[1];
    const float* wk  = (const float*)d_in[2];
    const float* wv  = (const float*)d_in[3];
    const float* wo  = (const float*)d_in[4];
    const float* ln1 = (const float*)d_in[5];
    const float* ln2 = (const float*)d_in[6];
    const float* w1  = (const float*)d_in[7];
    const float* b1  = (const float*)d_in[8];
    const float* w2  = (const float*)d_in[9];
    const float* b2  = (const float*)d_in[10];
    float* out = (float*)d_out;

    float *x1, *x2;
    __half *c, *q, *k, *v, *vT, *at, *h;
    __half *wqT, *wkT, *wvT, *woT, *w1T, *w2T;
    cudaGetSymbolAddress((void**)&x1, g_x1);
    cudaGetSymbolAddress((void**)&x2, g_x2);
    cudaGetSymbolAddress((void**)&c,  g_c);
    cudaGetSymbolAddress((void**)&q,  g_q);
    cudaGetSymbolAddress((void**)&k,  g_k);
    cudaGetSymbolAddress((void**)&v,  g_v);
    cudaGetSymbolAddress((void**)&vT, g_vT);
    cudaGetSymbolAddress((void**)&at, g_at);
    cudaGetSymbolAddress((void**)&h,  g_h);
    cudaGetSymbolAddress((void**)&wqT, g_wqT);
    cudaGetSymbolAddress((void**)&wkT, g_wkT);
    cudaGetSymbolAddress((void**)&wvT, g_wvT);
    cudaGetSymbolAddress((void**)&woT, g_woT);
    cudaGetSymbolAddress((void**)&w1T, g_w1T);
    cudaGetSymbolAddress((void**)&w2T, g_w2T);

    const int SM128 = (128 + 128) * 40 * 3 * 2;   // 61440
    const int SMFA  = (128 * QS_STRIDE + 512 * KS_STRIDE + 64 * VS_STRIDE) * 2;  // 158720

    static bool attr_done = false;
    if (!attr_done) {
        cudaFuncSetAttribute(gemm_kernel<128,128,64,32,0,__half>, cudaFuncAttributeMaxDynamicSharedMemorySize, SM128);
        cudaFuncSetAttribute(gemm_kernel<128,128,64,32,4,__half>, cudaFuncAttributeMaxDynamicSharedMemorySize, SM128);
        cudaFuncSetAttribute(gemm_kernel<128,128,64,32,1,__half>, cudaFuncAttributeMaxDynamicSharedMemorySize, SM128);
        cudaFuncSetAttribute(gemm_kernel<128,128,64,32,2,float >, cudaFuncAttributeMaxDynamicSharedMemorySize, SM128);
        cudaFuncSetAttribute(gemm_kernel<128,128,64,32,3,float >, cudaFuncAttributeMaxDynamicSharedMemorySize, SM128);
        cudaFuncSetAttribute(flash_kernel, cudaFuncAttributeMaxDynamicSharedMemorySize, SMFA);
        attr_done = true;
    }

    const long long rowStride = (long long)SEQ * DMODEL;
    const long long vTb = (long long)NHEAD * HDIM * SEQ;
    const long long vTh = (long long)HDIM * SEQ;

    dim3 tb(32, 8);

    // 0. weight prep: transpose + half convert
    transpose_h<float><<<dim3(DMODEL/32, DMODEL/32, 1), tb>>>(wq,0,0,DMODEL, wqT,0,0,DMODEL, 1);
    transpose_h<float><<<dim3(DMODEL/32, DMODEL/32, 1), tb>>>(wk,0,0,DMODEL, wkT,0,0,DMODEL, 1);
    transpose_h<float><<<dim3(DMODEL/32, DMODEL/32, 1), tb>>>(wv,0,0,DMODEL, wvT,0,0,DMODEL, 1);
    transpose_h<float><<<dim3(DMODEL/32, DMODEL/32, 1), tb>>>(wo,0,0,DMODEL, woT,0,0,DMODEL, 1);
    transpose_h<float><<<dim3(FFDIM/32,  DMODEL/32, 1), tb>>>(w1,0,0,FFDIM,  w1T,0,0,DMODEL, 1);
    transpose_h<float><<<dim3(DMODEL/32, FFDIM/32,  1), tb>>>(w2,0,0,DMODEL, w2T,0,0,FFDIM,  1);

    // 1. c = LN1(x)
    ln_kernel<<<ROWS, 256>>>(x, ln1, c);

    // 2. q/k/v = c @ w{q,k,v}   (q pre-scaled by 0.125)
    dim3 gA(DMODEL / 128, ROWS / 128, 1);
    gemm_kernel<128,128,64,32,4,__half><<<gA,256,SM128>>>(c,0,0,DMODEL, wqT,0,0,DMODEL, q,0,0,DMODEL, nullptr,nullptr, ROWS,DMODEL,DMODEL, 1);
    gemm_kernel<128,128,64,32,0,__half><<<gA,256,SM128>>>(c,0,0,DMODEL, wkT,0,0,DMODEL, k,0,0,DMODEL, nullptr,nullptr, ROWS,DMODEL,DMODEL, 1);
    gemm_kernel<128,128,64,32,0,__half><<<gA,256,SM128>>>(c,0,0,DMODEL, wvT,0,0,DMODEL, v,0,0,DMODEL, nullptr,nullptr, ROWS,DMODEL,DMODEL, 1);

    // 2b. vT[b,h][d][j] = v[b][j][h*64+d]
    transpose_h<__half><<<dim3(HDIM/32, SEQ/32, BATCH*NHEAD), tb>>>(
        v, rowStride, (long long)HDIM, DMODEL, vT, vTb, vTh, SEQ, NHEAD);

    // 3-5. fused attention
    flash_kernel<<<dim3(SEQ/128, BATCH*NHEAD), 256, SMFA>>>(q, k, vT, at);

    // 6. x1 = x + 2*(at @ wo)
    gemm_kernel<128,128,64,32,3,float><<<gA,256,SM128>>>(at,0,0,DMODEL, woT,0,0,DMODEL, x1,0,0,DMODEL, nullptr, x, ROWS,DMODEL,DMODEL, 1);

    // 7-9. MLP #1
    ln_kernel<<<ROWS, 256>>>(x1, ln2, c);
    dim3 gF(FFDIM / 128, ROWS / 128, 1);
    gemm_kernel<128,128,64,32,1,__half><<<gF,256,SM128>>>(c,0,0,DMODEL, w1T,0,0,DMODEL, h,0,0,FFDIM, b1, nullptr, ROWS,FFDIM,DMODEL, 1);
    gemm_kernel<128,128,64,32,2,float ><<<gA,256,SM128>>>(h,0,0,FFDIM, w2T,0,0,FFDIM, x2,0,0,DMODEL, b2, x1, ROWS,DMODEL,FFDIM, 1);

    // 10-12. MLP #2
    ln_kernel<<<ROWS, 256>>>(x2, ln2, c);
    gemm_kernel<128,128,64,32,1,__half><<<gF,256,SM128>>>(c,0,0,DMODEL, w1T,0,0,DMODEL, h,0,0,FFDIM, b1, nullptr, ROWS,FFDIM,DMODEL, 1);
    gemm_kernel<128,128,64,32,2,float ><<<gA,256,SM128>>>(h,0,0,FFDIM, w2T,0,0,FFDIM, out,0,0,DMODEL, b2, x2, ROWS,DMODEL,FFDIM, 1);
}

// round 7
// speedup vs baseline: 3.2874x; 1.2007x over previous
#include <cuda_runtime.h>
#include <cuda_fp16.h>
#include <math.h>
#include <stdint.h>

// ---------------------------------------------------------------------------
// Transformer block: B=16, S=512, D=1024, H=16, HD=64, FF=4096
// FP16 tensor-core GEMMs (mma.sync.m16n8k16 + ldmatrix.x4, fp32 accumulate),
// 4-stage cp.async pipeline, fused flash-attention.
// ---------------------------------------------------------------------------

#define BATCH   16
#define SEQ     512
#define DMODEL  1024
#define NHEAD   16
#define HDIM    64
#define FFDIM   4096
#define ROWS    (BATCH * SEQ)          // 8192

// fp32 spine
__device__ float  g_x1 [ROWS * DMODEL];
__device__ float  g_x2 [ROWS * DMODEL];
// half operands
__device__ __half g_c  [ROWS * DMODEL];
__device__ __half g_q  [ROWS * DMODEL];
__device__ __half g_k  [ROWS * DMODEL];
__device__ __half g_v  [ROWS * DMODEL];
__device__ __half g_vT [ROWS * DMODEL];                      // [b,h][d][j]
__device__ __half g_at [ROWS * DMODEL];
__device__ __half g_h  [ROWS * FFDIM];
// transposed half weights
__device__ __half g_wqT[DMODEL * DMODEL];
__device__ __half g_wkT[DMODEL * DMODEL];
__device__ __half g_wvT[DMODEL * DMODEL];
__device__ __half g_woT[DMODEL * DMODEL];
__device__ __half g_w1T[(size_t)DMODEL * FFDIM];
__device__ __half g_w2T[(size_t)DMODEL * FFDIM];

// ---------------------------------------------------------------------------
__device__ __forceinline__ float gelu_tanh(float x) {
    float x3 = x * x * x;
    float u  = 0.7978845608028654f * (x + 0.044715f * x3);
    return 0.5f * x * (1.0f + tanhf(u));
}

__device__ __forceinline__ void mma_f16(float* c, const uint32_t* a, const uint32_t* b) {
    asm volatile(
        "mma.sync.aligned.m16n8k16.row.col.f32.f16.f16.f32 "
        "{%0,%1,%2,%3}, {%4,%5,%6,%7}, {%8,%9}, {%0,%1,%2,%3};\n"
        : "+f"(c[0]), "+f"(c[1]), "+f"(c[2]), "+f"(c[3])
        : "r"(a[0]), "r"(a[1]), "r"(a[2]), "r"(a[3]),
          "r"(b[0]), "r"(b[1]));
}

__device__ __forceinline__ void ldm_x4(uint32_t* r, uint32_t addr) {
    asm volatile(
        "ldmatrix.sync.aligned.m8n8.x4.shared.b16 {%0,%1,%2,%3}, [%4];"
        : "=r"(r[0]), "=r"(r[1]), "=r"(r[2]), "=r"(r[3]) : "r"(addr));
}

__device__ __forceinline__ void cp16(uint32_t dst, const void* src) {
    asm volatile("cp.async.cg.shared.global [%0], [%1], 16;\n" :: "r"(dst), "l"(src));
}
__device__ __forceinline__ void cp_commit() {
    asm volatile("cp.async.commit_group;\n");
}
template<int N>
__device__ __forceinline__ void cp_wait() {
    asm volatile("cp.async.wait_group %0;\n" :: "n"(N));
}

__device__ __forceinline__ uint32_t packh2(float a, float b) {
    __half2 h = __floats2half2_rn(a, b);
    return *(uint32_t*)&h;
}

// ---------------------------------------------------------------------------
// Batched transpose -> half
// ---------------------------------------------------------------------------
template<typename TIN>
__global__ void transpose_h(const TIN* __restrict__ in, long long iOuter, long long iInner, int ldin,
                            __half* __restrict__ out, long long oOuter, long long oInner, int ldout,
                            int ic) {
    __shared__ float t[32][33];
    int z = blockIdx.z;
    const TIN* ib = in  + (z / ic) * iOuter + (z % ic) * iInner;
    __half*    ob = out + (z / ic) * oOuter + (z % ic) * oInner;
    int r0 = blockIdx.y * 32, c0 = blockIdx.x * 32;
    #pragma unroll
    for (int j = 0; j < 32; j += 8)
        t[threadIdx.y + j][threadIdx.x] = (float)ib[(size_t)(r0 + threadIdx.y + j) * ldin + c0 + threadIdx.x];
    __syncthreads();
    #pragma unroll
    for (int j = 0; j < 32; j += 8)
        ob[(size_t)(c0 + threadIdx.y + j) * ldout + r0 + threadIdx.x] =
            __float2half_rn(t[threadIdx.x][threadIdx.y + j]);
}

// ---------------------------------------------------------------------------
// LayerNorm: one block per row of 1024, half output
// ---------------------------------------------------------------------------
__global__ void ln_kernel(const float* __restrict__ x,
                          const float* __restrict__ scale,
                          __half* __restrict__ out) {
    int row = blockIdx.x, tid = threadIdx.x;
    const float4* xr = (const float4*)(x + (size_t)row * DMODEL);
    float4 v = xr[tid];
    float s = v.x + v.y + v.z + v.w;
    float q = v.x * v.x + v.y * v.y + v.z * v.z + v.w * v.w;
    #pragma unroll
    for (int o = 16; o > 0; o >>= 1) {
        s += __shfl_xor_sync(0xffffffffu, s, o);
        q += __shfl_xor_sync(0xffffffffu, q, o);
    }
    __shared__ float ss[8], qq[8];
    if ((tid & 31) == 0) { ss[tid >> 5] = s; qq[tid >> 5] = q; }
    __syncthreads();
    if (tid == 0) {
        float ts = 0.f, tq = 0.f;
        #pragma unroll
        for (int i = 0; i < 8; i++) { ts += ss[i]; tq += qq[i]; }
        ss[0] = ts; qq[0] = tq;
    }
    __syncthreads();
    float mean = ss[0] * (1.0f / DMODEL);
    float var  = qq[0] * (1.0f / DMODEL) - mean * mean;
    float r    = rsqrtf(var + 1e-6f);
    float4 sc  = ((const float4*)scale)[tid];
    __half2 o0 = __floats2half2_rn((v.x - mean) * r * sc.x, (v.y - mean) * r * sc.y);
    __half2 o1 = __floats2half2_rn((v.z - mean) * r * sc.z, (v.w - mean) * r * sc.w);
    __half2* op = (__half2*)(out + (size_t)row * DMODEL + tid * 4);
    op[0] = o0; op[1] = o1;
}

// ---------------------------------------------------------------------------
// Fused flash attention (ldmatrix fragment loads).
// grid = (S/128, B*H), 256 threads; q pre-scaled by 1/8.
// ---------------------------------------------------------------------------
#define QS_STRIDE 72
#define KS_STRIDE 72
#define VS_STRIDE 520

__global__ void __launch_bounds__(256, 1)
flash_kernel(const __half* __restrict__ q, const __half* __restrict__ k,
             const __half* __restrict__ vT, __half* __restrict__ at) {
    extern __shared__ __half sm[];
    __half* Qs = sm;                               // 128 x 72
    __half* Ks = Qs + 128 * QS_STRIDE;             // 512 x 72
    __half* Vs = Ks + 512 * KS_STRIDE;             // 64 x 520

    int bh = blockIdx.y;
    int b  = bh >> 4;
    int h  = bh & 15;
    int i0 = blockIdx.x * 128;

    const __half* Qg = q  + ((size_t)(b * SEQ + i0)) * DMODEL + h * HDIM;
    const __half* Kg = k  + ((size_t)(b * SEQ))      * DMODEL + h * HDIM;
    const __half* Vg = vT + ((size_t)b * NHEAD + h) * HDIM * SEQ;

    int tid = threadIdx.x;
    uint32_t Qsb = (uint32_t)__cvta_generic_to_shared(Qs);
    uint32_t Ksb = (uint32_t)__cvta_generic_to_shared(Ks);
    uint32_t Vsb = (uint32_t)__cvta_generic_to_shared(Vs);

    #pragma unroll
    for (int i = 0; i < 4; i++) {
        int idx = tid + i * 256;
        int r = idx >> 3, c = idx & 7;
        cp16(Qsb + (uint32_t)(r * QS_STRIDE + c * 8) * 2u, Qg + (size_t)r * DMODEL + c * 8);
    }
    #pragma unroll
    for (int i = 0; i < 16; i++) {
        int idx = tid + i * 256;
        int r = idx >> 3, c = idx & 7;
        cp16(Ksb + (uint32_t)(r * KS_STRIDE + c * 8) * 2u, Kg + (size_t)r * DMODEL + c * 8);
    }
    #pragma unroll
    for (int i = 0; i < 16; i++) {
        int idx = tid + i * 256;
        int r = idx >> 6, c = idx & 63;
        cp16(Vsb + (uint32_t)(r * VS_STRIDE + c * 8) * 2u, Vg + (size_t)r * SEQ + c * 8);
    }
    cp_commit();
    cp_wait<0>();
    __syncthreads();

    int warp = tid >> 5, lane = tid & 31;
    int g = lane >> 2, tc = lane & 3;
    int wr = warp * 16;
    int lane16 = lane & 15, laneHi = lane >> 4;      // ldmatrix addressing
    int bRow   = laneHi * 8 + (lane & 7);            // B-fragment row within pair
    int bKoff  = ((lane >> 3) & 1) * 8;              // B-fragment k offset

    // ldmatrix base addresses (bytes)
    uint32_t qLdm = Qsb + (uint32_t)((wr + lane16) * QS_STRIDE + laneHi * 8) * 2u;
    uint32_t kLdm = Ksb + (uint32_t)(bRow * KS_STRIDE + bKoff) * 2u;
    uint32_t vLdm = Vsb + (uint32_t)(bRow * VS_STRIDE + bKoff) * 2u;

    float m0 = -1e30f, m1 = -1e30f, l0 = 0.f, l1 = 0.f;
    float O[8][4];
    #pragma unroll
    for (int dt = 0; dt < 8; dt++)
        #pragma unroll
        for (int e = 0; e < 4; e++) O[dt][e] = 0.f;

    for (int jc = 0; jc < 4; jc++) {
        int j0 = jc * 128;
        float S[16][4];
        #pragma unroll
        for (int nt = 0; nt < 16; nt++)
            #pragma unroll
            for (int e = 0; e < 4; e++) S[nt][e] = 0.f;

        // S = Q @ K^T
        #pragma unroll
        for (int ks = 0; ks < 4; ks++) {
            uint32_t a[4];
            ldm_x4(a, qLdm + (uint32_t)(ks * 16) * 2u);
            #pragma unroll
            for (int p = 0; p < 8; p++) {            // nt pairs
                uint32_t bb[4];
                ldm_x4(bb, kLdm + (uint32_t)((j0 + p * 16) * KS_STRIDE + ks * 16) * 2u);
                mma_f16(S[2*p    ], a, bb);
                mma_f16(S[2*p + 1], a, bb + 2);
            }
        }

        // online softmax
        float mx0 = -1e30f, mx1 = -1e30f;
        #pragma unroll
        for (int nt = 0; nt < 16; nt++) {
            mx0 = fmaxf(mx0, fmaxf(S[nt][0], S[nt][1]));
            mx1 = fmaxf(mx1, fmaxf(S[nt][2], S[nt][3]));
        }
        mx0 = fmaxf(mx0, __shfl_xor_sync(0xffffffffu, mx0, 1));
        mx0 = fmaxf(mx0, __shfl_xor_sync(0xffffffffu, mx0, 2));
        mx1 = fmaxf(mx1, __shfl_xor_sync(0xffffffffu, mx1, 1));
        mx1 = fmaxf(mx1, __shfl_xor_sync(0xffffffffu, mx1, 2));
        float mn0 = fmaxf(m0, mx0), mn1 = fmaxf(m1, mx1);
        float al0 = __expf(m0 - mn0), al1 = __expf(m1 - mn1);
        m0 = mn0; m1 = mn1;

        float rs0 = 0.f, rs1 = 0.f;
        #pragma unroll
        for (int nt = 0; nt < 16; nt++) {
            S[nt][0] = __expf(S[nt][0] - mn0);
            S[nt][1] = __expf(S[nt][1] - mn0);
            S[nt][2] = __expf(S[nt][2] - mn1);
            S[nt][3] = __expf(S[nt][3] - mn1);
            rs0 += S[nt][0] + S[nt][1];
            rs1 += S[nt][2] + S[nt][3];
        }
        rs0 += __shfl_xor_sync(0xffffffffu, rs0, 1);
        rs0 += __shfl_xor_sync(0xffffffffu, rs0, 2);
        rs1 += __shfl_xor_sync(0xffffffffu, rs1, 1);
        rs1 += __shfl_xor_sync(0xffffffffu, rs1, 2);
        l0 = l0 * al0 + rs0;
        l1 = l1 * al1 + rs1;

        #pragma unroll
        for (int dt = 0; dt < 8; dt++) {
            O[dt][0] *= al0; O[dt][1] *= al0;
            O[dt][2] *= al1; O[dt][3] *= al1;
        }

        // O += P @ V
        #pragma unroll
        for (int kp = 0; kp < 8; kp++) {
            uint32_t a[4];
            a[0] = packh2(S[2*kp  ][0], S[2*kp  ][1]);
            a[1] = packh2(S[2*kp  ][2], S[2*kp  ][3]);
            a[2] = packh2(S[2*kp+1][0], S[2*kp+1][1]);
            a[3] = packh2(S[2*kp+1][2], S[2*kp+1][3]);
            #pragma unroll
            for (int p = 0; p < 4; p++) {            // dt pairs
                uint32_t bb[4];
                ldm_x4(bb, vLdm + (uint32_t)(p * 16 * VS_STRIDE + j0 + kp * 16) * 2u);
                mma_f16(O[2*p    ], a, bb);
                mma_f16(O[2*p + 1], a, bb + 2);
            }
        }
    }

    float inv0 = 1.0f / l0, inv1 = 1.0f / l1;
    int row0 = b * SEQ + i0 + wr + g;
    __half* ob = at + (size_t)row0 * DMODEL + h * HDIM;
    #pragma unroll
    for (int dt = 0; dt < 8; dt++) {
        __half2 o0 = __floats2half2_rn(O[dt][0] * inv0, O[dt][1] * inv0);
        __half2 o1 = __floats2half2_rn(O[dt][2] * inv1, O[dt][3] * inv1);
        *(__half2*)(ob + dt * 8 + tc * 2)                        = o0;
        *(__half2*)(ob + (size_t)8 * DMODEL + dt * 8 + tc * 2)   = o1;
    }
}

// ---------------------------------------------------------------------------
// Batched FP16 GEMM, fp32 accumulate, 4-stage cp.async pipeline, ldmatrix.
// C[M,N] = A[M,K] * B^T, A [M,K], B [N,K], half, K-contiguous.
// EPI: 0 none | 1 gelu(acc+bias) | 2 acc+bias+res | 3 res+2*acc | 4 acc*0.125
// ---------------------------------------------------------------------------
template<int BM, int BN, int WM, int WN, int EPI, typename OUT>
__global__ void __launch_bounds__(256, 2)
gemm_kernel(const __half* __restrict__ A, long long aOuter, long long aInner, int lda,
            const __half* __restrict__ B, long long bOuter, long long bInner, int ldb,
            OUT* __restrict__ C, long long cOuter, long long cInner, int ldc,
            const float* __restrict__ bias,
            const float* __restrict__ res,
            int M, int N, int K, int innerCount) {
    constexpr int BK = 32;
    constexpr int NSTAGES = 4;
    constexpr int WARPS_M = BM / WM;
    constexpr int WARPS_N = BN / WN;
    static_assert(WARPS_M * WARPS_N == 8, "8 warps");
    constexpr int MT = WM / 16;
    constexpr int NT = WN / 8;
    static_assert(NT % 2 == 0, "NT even for ldmatrix pairs");
    constexpr int STRIDE = BK + 8;
    constexpr int A_H = BM * STRIDE;
    constexpr int B_H = BN * STRIDE;
    constexpr int STAGE_H = A_H + B_H;

    extern __shared__ __half smem[];
    uint32_t smem_u32 = (uint32_t)__cvta_generic_to_shared(smem);

    int z  = blockIdx.z;
    int zo = z / innerCount, zi = z % innerCount;
    const __half* Ab = A + zo * aOuter + zi * aInner;
    const __half* Bb = B + zo * bOuter + zi * bInner;
    OUT*          Cb = C + zo * cOuter + zi * cInner;
    const float*  Rb = (EPI == 2 || EPI == 3) ? (res + zo * cOuter + zi * cInner) : nullptr;

    int m0 = blockIdx.y * BM;
    int n0 = blockIdx.x * BN;

    int tid  = threadIdx.x;
    int warp = tid >> 5, lane = tid & 31;
    int wm = (warp % WARPS_M) * WM;
    int wn = (warp / WARPS_M) * WN;
    int g  = lane >> 2, tc = lane & 3;
    int lane16 = lane & 15, laneHi = lane >> 4;
    int bRow   = laneHi * 8 + (lane & 7);
    int bKoff  = ((lane >> 3) & 1) * 8;

    // ldmatrix base byte offsets (within stage 0)
    uint32_t aLdm = smem_u32 + (uint32_t)((wm + lane16) * STRIDE + laneHi * 8) * 2u;
    uint32_t bLdm = smem_u32 + (uint32_t)A_H * 2u
                  + (uint32_t)((wn + bRow) * STRIDE + bKoff) * 2u;

    int l_r  = tid >> 2;
    int l_k8 = tid & 3;
    const __half* Aptr = Ab + (size_t)(m0 + l_r) * lda + l_k8 * 8;
    const __half* Bptr = Bb + (size_t)(n0 + l_r) * ldb + l_k8 * 8;

    float acc[MT][NT][4];
    #pragma unroll
    for (int i = 0; i < MT; i++)
        #pragma unroll
        for (int j = 0; j < NT; j++)
            #pragma unroll
            for (int e = 0; e < 4; e++) acc[i][j][e] = 0.f;

    const int ntiles = K / BK;

    auto load_tile = [&](int t, int s) {
        int kt = t * BK;
        uint32_t aBase = smem_u32 + (uint32_t)(s * STAGE_H) * 2u;
        uint32_t bBase = aBase + (uint32_t)A_H * 2u;
        #pragma unroll
        for (int i = 0; i < BM / 64; ++i)
            cp16(aBase + (uint32_t)((l_r + i * 64) * STRIDE + l_k8 * 8) * 2u,
                 Aptr + (size_t)(i * 64) * lda + kt);
        #pragma unroll
        for (int i = 0; i < BN / 64; ++i)
            cp16(bBase + (uint32_t)((l_r + i * 64) * STRIDE + l_k8 * 8) * 2u,
                 Bptr + (size_t)(i * 64) * ldb + kt);
    };

    #pragma unroll
    for (int s = 0; s < NSTAGES - 1; ++s) {
        if (s < ntiles) load_tile(s, s);
        cp_commit();
    }

    for (int t = 0; t < ntiles; ++t) {
        cp_wait<NSTAGES - 2>();
        __syncthreads();

        int tn = t + NSTAGES - 1;
        if (tn < ntiles) load_tile(tn, tn % NSTAGES);
        cp_commit();

        uint32_t stOff = (uint32_t)((t % NSTAGES) * STAGE_H) * 2u;

        #pragma unroll
        for (int ks = 0; ks < BK / 16; ++ks) {
            uint32_t af[MT][4], bf[NT][2];
            #pragma unroll
            for (int mt = 0; mt < MT; ++mt)
                ldm_x4(af[mt], aLdm + stOff + (uint32_t)(mt * 16 * STRIDE + ks * 16) * 2u);
            #pragma unroll
            for (int p = 0; p < NT / 2; ++p) {
                uint32_t bb[4];
                ldm_x4(bb, bLdm + stOff + (uint32_t)(p * 16 * STRIDE + ks * 16) * 2u);
                bf[2*p    ][0] = bb[0]; bf[2*p    ][1] = bb[1];
                bf[2*p + 1][0] = bb[2]; bf[2*p + 1][1] = bb[3];
            }
            #pragma unroll
            for (int mt = 0; mt < MT; ++mt)
                #pragma unroll
                for (int nt = 0; nt < NT; ++nt)
                    mma_f16(acc[mt][nt], af[mt], bf[nt]);
        }
    }

    // ---- epilogue ----
    #pragma unroll
    for (int mt = 0; mt < MT; ++mt) {
        #pragma unroll
        for (int nt = 0; nt < NT; ++nt) {
            int col = n0 + wn + nt * 8 + tc * 2;
            #pragma unroll
            for (int hrow = 0; hrow < 2; ++hrow) {
                int row  = m0 + wm + mt * 16 + g + hrow * 8;
                float v0 = acc[mt][nt][hrow * 2 + 0];
                float v1 = acc[mt][nt][hrow * 2 + 1];
                size_t off = (size_t)row * ldc + col;
                if (EPI == 1) {
                    v0 = gelu_tanh(v0 + bias[col]);
                    v1 = gelu_tanh(v1 + bias[col + 1]);
                } else if (EPI == 2) {
                    v0 = v0 + bias[col]     + Rb[off];
                    v1 = v1 + bias[col + 1] + Rb[off + 1];
                } else if (EPI == 3) {
                    v0 = 2.0f * v0 + Rb[off];
                    v1 = 2.0f * v1 + Rb[off + 1];
                } else if (EPI == 4) {
                    v0 *= 0.125f;
                    v1 *= 0.125f;
                }
                if (sizeof(OUT) == 2) {
                    *(__half2*)((__half*)Cb + off) = __floats2half2_rn(v0, v1);
                } else {
                    *(float2*)((float*)Cb + off) = make_float2(v0, v1);
                }
            }
        }
    }
}

// ---------------------------------------------------------------------------
// host launch
// ---------------------------------------------------------------------------
extern "C" void kernel_launch(void* const* d_in, const int* in_sizes, int n_in,
                              void* d_out, int out_size) {
    const float* x   = (const float*)d_in[0];
    const float* wq  = (const float*)d_in[1];
    const float* wk  = (const float*)d_in[2];
    const float* wv  = (const float*)d_in[3];
    const float* wo  = (const float*)d_in[4];
    const float* ln1 = (const float*)d_in[5];
    const float* ln2 = (const float*)d_in[6];
    const float* w1  = (const float*)d_in[7];
    const float* b1  = (const float*)d_in[8];
    const float* w2  = (const float*)d_in[9];
    const float* b2  = (const float*)d_in[10];
    float* out = (float*)d_out;

    float *x1, *x2;
    __half *c, *q, *k, *v, *vT, *at, *h;
    __half *wqT, *wkT, *wvT, *woT, *w1T, *w2T;
    cudaGetSymbolAddress((void**)&x1, g_x1);
    cudaGetSymbolAddress((void**)&x2, g_x2);
    cudaGetSymbolAddress((void**)&c,  g_c);
    cudaGetSymbolAddress((void**)&q,  g_q);
    cudaGetSymbolAddress((void**)&k,  g_k);
    cudaGetSymbolAddress((void**)&v,  g_v);
    cudaGetSymbolAddress((void**)&vT, g_vT);
    cudaGetSymbolAddress((void**)&at, g_at);
    cudaGetSymbolAddress((void**)&h,  g_h);
    cudaGetSymbolAddress((void**)&wqT, g_wqT);
    cudaGetSymbolAddress((void**)&wkT, g_wkT);
    cudaGetSymbolAddress((void**)&wvT, g_wvT);
    cudaGetSymbolAddress((void**)&woT, g_woT);
    cudaGetSymbolAddress((void**)&w1T, g_w1T);
    cudaGetSymbolAddress((void**)&w2T, g_w2T);

    const int SM128 = (128 + 128) * 40 * 4 * 2;   // 81920 (4 stages)
    const int SMFA  = (128 * QS_STRIDE + 512 * KS_STRIDE + 64 * VS_STRIDE) * 2;  // 158720

    static bool attr_done = false;
    if (!attr_done) {
        cudaFuncSetAttribute(gemm_kernel<128,128,64,32,0,__half>, cudaFuncAttributeMaxDynamicSharedMemorySize, SM128);
        cudaFuncSetAttribute(gemm_kernel<128,128,64,32,4,__half>, cudaFuncAttributeMaxDynamicSharedMemorySize, SM128);
        cudaFuncSetAttribute(gemm_kernel<128,128,64,32,1,__half>, cudaFuncAttributeMaxDynamicSharedMemorySize, SM128);
        cudaFuncSetAttribute(gemm_kernel<128,128,64,32,2,float >, cudaFuncAttributeMaxDynamicSharedMemorySize, SM128);
        cudaFuncSetAttribute(gemm_kernel<128,128,64,32,3,float >, cudaFuncAttributeMaxDynamicSharedMemorySize, SM128);
        cudaFuncSetAttribute(flash_kernel, cudaFuncAttributeMaxDynamicSharedMemorySize, SMFA);
        attr_done = true;
    }

    const long long rowStride = (long long)SEQ * DMODEL;
    const long long vTb = (long long)NHEAD * HDIM * SEQ;
    const long long vTh = (long long)HDIM * SEQ;

    dim3 tb(32, 8);

    // 0. weight prep: transpose + half convert
    transpose_h<float><<<dim3(DMODEL/32, DMODEL/32, 1), tb>>>(wq,0,0,DMODEL, wqT,0,0,DMODEL, 1);
    transpose_h<float><<<dim3(DMODEL/32, DMODEL/32, 1), tb>>>(wk,0,0,DMODEL, wkT,0,0,DMODEL, 1);
    transpose_h<float><<<dim3(DMODEL/32, DMODEL/32, 1), tb>>>(wv,0,0,DMODEL, wvT,0,0,DMODEL, 1);
    transpose_h<float><<<dim3(DMODEL/32, DMODEL/32, 1), tb>>>(wo,0,0,DMODEL, woT,0,0,DMODEL, 1);
    transpose_h<float><<<dim3(FFDIM/32,  DMODEL/32, 1), tb>>>(w1,0,0,FFDIM,  w1T,0,0,DMODEL, 1);
    transpose_h<float><<<dim3(DMODEL/32, FFDIM/32,  1), tb>>>(w2,0,0,DMODEL, w2T,0,0,FFDIM,  1);

    // 1. c = LN1(x)
    ln_kernel<<<ROWS, 256>>>(x, ln1, c);

    // 2. q/k/v = c @ w{q,k,v}   (q pre-scaled by 0.125)
    dim3 gA(DMODEL / 128, ROWS / 128, 1);
    gemm_kernel<128,128,64,32,4,__half><<<gA,256,SM128>>>(c,0,0,DMODEL, wqT,0,0,DMODEL, q,0,0,DMODEL, nullptr,nullptr, ROWS,DMODEL,DMODEL, 1);
    gemm_kernel<128,128,64,32,0,__half><<<gA,256,SM128>>>(c,0,0,DMODEL, wkT,0,0,DMODEL, k,0,0,DMODEL, nullptr,nullptr, ROWS,DMODEL,DMODEL, 1);
    gemm_kernel<128,128,64,32,0,__half><<<gA,256,SM128>>>(c,0,0,DMODEL, wvT,0,0,DMODEL, v,0,0,DMODEL, nullptr,nullptr, ROWS,DMODEL,DMODEL, 1);

    // 2b. vT[b,h][d][j] = v[b][j][h*64+d]
    transpose_h<__half><<<dim3(HDIM/32, SEQ/32, BATCH*NHEAD), tb>>>(
        v, rowStride, (long long)HDIM, DMODEL, vT, vTb, vTh, SEQ, NHEAD);

    // 3-5. fused attention
    flash_kernel<<<dim3(SEQ/128, BATCH*NHEAD), 256, SMFA>>>(q, k, vT, at);

    // 6. x1 = x + 2*(at @ wo)
    gemm_kernel<128,128,64,32,3,float><<<gA,256,SM128>>>(at,0,0,DMODEL, woT,0,0,DMODEL, x1,0,0,DMODEL, nullptr, x, ROWS,DMODEL,DMODEL, 1);

    // 7-9. MLP #1
    ln_kernel<<<ROWS, 256>>>(x1, ln2, c);
    dim3 gF(FFDIM / 128, ROWS / 128, 1);
    gemm_kernel<128,128,64,32,1,__half><<<gF,256,SM128>>>(c,0,0,DMODEL, w1T,0,0,DMODEL, h,0,0,FFDIM, b1, nullptr, ROWS,FFDIM,DMODEL, 1);
    gemm_kernel<128,128,64,32,2,float ><<<gA,256,SM128>>>(h,0,0,FFDIM, w2T,0,0,FFDIM, x2,0,0,DMODEL, b2, x1, ROWS,DMODEL,FFDIM, 1);

    // 10-12. MLP #2
    ln_kernel<<<ROWS, 256>>>(x2, ln2, c);
    gemm_kernel<128,128,64,32,1,__half><<<gF,256,SM128>>>(c,0,0,DMODEL, w1T,0,0,DMODEL, h,0,0,FFDIM, b1, nullptr, ROWS,FFDIM,DMODEL, 1);
    gemm_kernel<128,128,64,32,2,float ><<<gA,256,SM128>>>(h,0,0,FFDIM, w2T,0,0,FFDIM, out,0,0,DMODEL, b2, x2, ROWS,DMODEL,FFDIM, 1);
}